// round 3
// baseline (speedup 1.0000x reference)
#include <cuda_runtime.h>
#include <math.h>

#define B_    1024
#define HID   256
#define HGEN  512
#define VOC   5
#define EMBD  64
#define LMAX  100
#define NB    256     // persistent grid: 256 blocks
#define NTHR  128     // 128 threads/block, 8x8 microtile

typedef unsigned long long ull;

// ---------------- static device scratch ----------------
__device__ float g_y0[(size_t)2 * LMAX * B_ * 2 * HID];   // [seq][t][b][512] layer-0 outputs
__device__ float g_z [(size_t)4 * B_ * 4 * HGEN / 2];     // gate scratch
__device__ float g_c0[(size_t)4 * B_ * HID];
__device__ float g_h1[(size_t)4 * B_ * HID];
__device__ float g_c1[(size_t)4 * B_ * HID];
__device__ float g_tab0 [2 * VOC * 4 * HID];              // emb @ ctx0_Wih^T per dir
__device__ float g_tabg0[VOC * 4 * HGEN];                 // emb @ gen0_Wih^T
__device__ float g_h0d[(size_t)B_ * HGEN];
__device__ float g_c0d[(size_t)B_ * HGEN];
__device__ float g_h1d[(size_t)B_ * HGEN];
__device__ float g_c1d[(size_t)B_ * HGEN];
__device__ int   g_tok[B_];

// ---------------- software grid barrier ----------------
__device__ unsigned g_cnt;
__device__ volatile unsigned g_gen;

__device__ __forceinline__ void gbar() {
    __syncthreads();
    __threadfence();
    if (threadIdx.x == 0) {
        unsigned gen = g_gen;
        if (atomicAdd(&g_cnt, 1u) == NB - 1u) {
            g_cnt = 0;
            __threadfence();
            g_gen = gen + 1u;
        } else {
            while (g_gen == gen) { }
        }
        __threadfence();
    }
    __syncthreads();
}

// ---------------- packed f32x2 helpers (Blackwell FFMA2) ----------------
__device__ __forceinline__ ull ffma2(ull a, ull b, ull c) {
    ull d;
    asm("fma.rn.f32x2 %0, %1, %2, %3;" : "=l"(d) : "l"(a), "l"(b), "l"(c));
    return d;
}
__device__ __forceinline__ ull bcast2(float x) {
    ull d;
    asm("mov.b64 %0, {%1, %1};" : "=l"(d) : "f"(x));
    return d;
}

// ---------------- GEMM tile: Z[128x64] = A0@W0^T (+A1@W1^T), NT, K-contig ----------------
// 128 threads, 8x8 per thread. tx = tid&7 (8x8 cols), ty = tid>>3 (16x8 rows).
#define BM 128
#define BN 64
#define BKK 16

__device__ __forceinline__ void gemm_pair(
    const float* __restrict__ A, int lda,
    const float* __restrict__ W, int K,
    int rowBase, int colBase,
    ull (&acc)[4][8],
    float (*sA)[BM], float (*sB)[BN],
    int tid, int tx, int ty)
{
    for (int k0 = 0; k0 < K; k0 += BKK) {
        // A tile: 128 rows x 16 k = 512 float4, 4 per thread
        #pragma unroll
        for (int r = 0; r < 4; r++) {
            int idx = r * NTHR + tid;
            int row = idx >> 2;
            int kv  = (idx & 3) * 4;
            float4 v = *reinterpret_cast<const float4*>(A + (size_t)(rowBase + row) * lda + k0 + kv);
            sA[kv + 0][row] = v.x; sA[kv + 1][row] = v.y;
            sA[kv + 2][row] = v.z; sA[kv + 3][row] = v.w;
        }
        // W tile: 64 rows x 16 k = 256 float4, 2 per thread
        #pragma unroll
        for (int r = 0; r < 2; r++) {
            int idx = r * NTHR + tid;
            int row = idx >> 2;
            int kv  = (idx & 3) * 4;
            float4 v = *reinterpret_cast<const float4*>(W + (size_t)(colBase + row) * K + k0 + kv);
            sB[kv + 0][row] = v.x; sB[kv + 1][row] = v.y;
            sB[kv + 2][row] = v.z; sB[kv + 3][row] = v.w;
        }
        __syncthreads();
        #pragma unroll
        for (int k = 0; k < BKK; k++) {
            // 8 a-values = 4 packed M-row pairs (adjacent rows pack naturally)
            ulonglong2 t0 = *reinterpret_cast<const ulonglong2*>(&sA[k][ty * 8]);
            ulonglong2 t1 = *reinterpret_cast<const ulonglong2*>(&sA[k][ty * 8 + 4]);
            ull a2[4] = { t0.x, t0.y, t1.x, t1.y };
            float4 vb0 = *reinterpret_cast<const float4*>(&sB[k][tx * 8]);
            float4 vb1 = *reinterpret_cast<const float4*>(&sB[k][tx * 8 + 4]);
            ull b2[8] = { bcast2(vb0.x), bcast2(vb0.y), bcast2(vb0.z), bcast2(vb0.w),
                          bcast2(vb1.x), bcast2(vb1.y), bcast2(vb1.z), bcast2(vb1.w) };
            #pragma unroll
            for (int ip = 0; ip < 4; ip++)
                #pragma unroll
                for (int j = 0; j < 8; j++)
                    acc[ip][j] = ffma2(a2[ip], b2[j], acc[ip][j]);
        }
        __syncthreads();
    }
}

__device__ __forceinline__ void gemm_tile(
    const float* A0, int lda0, const float* W0, int K0,
    const float* A1, int lda1, const float* W1, int K1,
    float* Z, int N, int rowBase, int colBase,
    float (*sA)[BM], float (*sB)[BN])
{
    const int tid = threadIdx.x;
    const int tx = tid & 7, ty = tid >> 3;
    ull acc[4][8];
    #pragma unroll
    for (int i = 0; i < 4; i++)
        #pragma unroll
        for (int j = 0; j < 8; j++) acc[i][j] = 0ull;

    gemm_pair(A0, lda0, W0, K0, rowBase, colBase, acc, sA, sB, tid, tx, ty);
    if (K1 > 0)
        gemm_pair(A1, lda1, W1, K1, rowBase, colBase, acc, sA, sB, tid, tx, ty);

    #pragma unroll
    for (int ip = 0; ip < 4; ip++) {
        float lo[8], hi[8];
        #pragma unroll
        for (int j = 0; j < 8; j++) {
            float2 p = *reinterpret_cast<float2*>(&acc[ip][j]);
            lo[j] = p.x; hi[j] = p.y;
        }
        float* z0 = Z + (size_t)(rowBase + ty * 8 + 2 * ip) * N + colBase + tx * 8;
        float* z1 = z0 + N;
        *reinterpret_cast<float4*>(z0)     = make_float4(lo[0], lo[1], lo[2], lo[3]);
        *reinterpret_cast<float4*>(z0 + 4) = make_float4(lo[4], lo[5], lo[6], lo[7]);
        *reinterpret_cast<float4*>(z1)     = make_float4(hi[0], hi[1], hi[2], hi[3]);
        *reinterpret_cast<float4*>(z1 + 4) = make_float4(hi[4], hi[5], hi[6], hi[7]);
    }
}

__device__ __forceinline__ float sigf(float x) { return 1.f / (1.f + expf(-x)); }

// ---------------- setup: tables + zero state ----------------
__global__ void setup_kernel(const float* __restrict__ emb,
                             const float* __restrict__ c0Wih,
                             const float* __restrict__ g0Wih) {
    int idx = blockIdx.x * blockDim.x + threadIdx.x;
    int stride = gridDim.x * blockDim.x;
    for (int i = idx; i < 4 * B_ * HID; i += stride) { g_c0[i] = 0.f; g_c1[i] = 0.f; }
    for (int i = idx; i < B_ * HGEN; i += stride)    { g_c0d[i] = 0.f; g_c1d[i] = 0.f; }
    for (int i = idx; i < B_; i += stride)           g_tok[i] = 0;

    for (int i = idx; i < 2 * VOC * 4 * HID; i += stride) {
        int n = i % (4 * HID);
        int v = (i / (4 * HID)) % VOC;
        int d = i / (4 * HID * VOC);
        const float* e = emb + v * EMBD;
        const float* w = c0Wih + ((size_t)d * 4 * HID + n) * EMBD;
        float s = 0.f;
        #pragma unroll
        for (int k = 0; k < EMBD; k++) s += e[k] * w[k];
        g_tab0[i] = s;
    }
    for (int i = idx; i < VOC * 4 * HGEN; i += stride) {
        int n = i % (4 * HGEN);
        int v = i / (4 * HGEN);
        const float* e = emb + v * EMBD;
        const float* w = g0Wih + (size_t)n * EMBD;
        float s = 0.f;
        #pragma unroll
        for (int k = 0; k < EMBD; k++) s += e[k] * w[k];
        g_tabg0[i] = s;
    }
}

// ---------------- encoder: persistent ----------------
__global__ __launch_bounds__(NTHR, 2) void encoder_kernel(
    const int* __restrict__ leftC, const int* __restrict__ rightC,
    const float* __restrict__ c0Whh, const float* __restrict__ c0b,
    const float* __restrict__ c1Wih, const float* __restrict__ c1Whh,
    const float* __restrict__ c1b, int L)
{
    __shared__ float sA[BKK][BM];
    __shared__ float sB[BKK][BN];
    const int bid = blockIdx.x, tid = threadIdx.x;

    // -------- layer 0: 4 units (seq x dir), L steps --------
    for (int t = 0; t < L; t++) {
        if (t > 0) {
            for (int tile = bid; tile < 512; tile += NB) {
                int u = tile >> 7, rem = tile & 127;
                int mt = rem >> 4, nt = rem & 15;          // 8 x 16 tiles (128x64)
                int seq = u >> 1, dir = u & 1;
                int time  = dir ? (L - 1 - t) : t;
                int ptime = dir ? (time + 1) : (time - 1);
                const float* A0 = g_y0 + ((size_t)(seq * LMAX + ptime) * B_) * (2 * HID) + dir * HID;
                const float* W0 = c0Whh + (size_t)dir * 4 * HID * HID;
                gemm_tile(A0, 2 * HID, W0, HID, nullptr, 0, nullptr, 0,
                          g_z + (size_t)u * B_ * 4 * HID, 4 * HID, mt * BM, nt * BN, sA, sB);
            }
            gbar();
        }
        for (int idx = bid * NTHR + tid; idx < 4 * B_ * HID; idx += NB * NTHR) {
            int u = idx / (B_ * HID), rem = idx % (B_ * HID);
            int b = rem / HID, j = rem % HID;
            int seq = u >> 1, dir = u & 1;
            int time = dir ? (L - 1 - t) : t;
            const int* ctx = seq ? rightC : leftC;
            int v = ctx[b * L + time];
            const float* tr = g_tab0 + ((size_t)dir * VOC + v) * (4 * HID);
            const float* bb = c0b + (size_t)dir * 4 * HID;
            float zi = tr[j] + bb[j];
            float zf = tr[HID + j] + bb[HID + j];
            float zg = tr[2 * HID + j] + bb[2 * HID + j];
            float zo = tr[3 * HID + j] + bb[3 * HID + j];
            float cprev = 0.f;
            if (t > 0) {
                const float* zr = g_z + ((size_t)u * B_ + b) * 4 * HID;
                zi += zr[j]; zf += zr[HID + j]; zg += zr[2 * HID + j]; zo += zr[3 * HID + j];
                cprev = g_c0[(size_t)u * B_ * HID + rem];
            }
            float c = sigf(zf) * cprev + sigf(zi) * tanhf(zg);
            g_c0[(size_t)u * B_ * HID + rem] = c;
            g_y0[((size_t)(seq * LMAX + time) * B_ + b) * (2 * HID) + dir * HID + j] = sigf(zo) * tanhf(c);
        }
        gbar();
    }

    // -------- layer 1: u0=left-fwd(full), u1=right-bwd(full), u2=left-bwd(1), u3=right-fwd(1) --------
    for (int s = 0; s < L; s++) {
        int nu = s ? 2 : 4;
        for (int tile = bid; tile < nu * 128; tile += NB) {
            int u = tile >> 7, rem = tile & 127;
            int mt = rem >> 4, nt = rem & 15;
            int seq = (u == 0 || u == 2) ? 0 : 1;
            int dir = (u == 1 || u == 2) ? 1 : 0;
            int time = dir ? (L - 1 - s) : s;
            const float* A0 = g_y0 + ((size_t)(seq * LMAX + time) * B_) * (2 * HID);
            const float* W0 = c1Wih + (size_t)dir * 4 * HID * 2 * HID;
            const float* A1 = nullptr; const float* W1 = nullptr; int K1 = 0;
            if (s) { A1 = g_h1 + (size_t)u * B_ * HID; W1 = c1Whh + (size_t)dir * 4 * HID * HID; K1 = HID; }
            gemm_tile(A0, 2 * HID, W0, 2 * HID, A1, HID, W1, K1,
                      g_z + (size_t)u * B_ * 4 * HID, 4 * HID, mt * BM, nt * BN, sA, sB);
        }
        gbar();
        for (int idx = bid * NTHR + tid; idx < nu * B_ * HID; idx += NB * NTHR) {
            int u = idx / (B_ * HID), rem = idx % (B_ * HID);
            int b = rem / HID, j = rem % HID;
            int dir = (u == 1 || u == 2) ? 1 : 0;
            const float* zr = g_z + ((size_t)u * B_ + b) * 4 * HID;
            const float* bb = c1b + (size_t)dir * 4 * HID;
            float zi = zr[j] + bb[j];
            float zf = zr[HID + j] + bb[HID + j];
            float zg = zr[2 * HID + j] + bb[2 * HID + j];
            float zo = zr[3 * HID + j] + bb[3 * HID + j];
            float cprev = s ? g_c1[(size_t)u * B_ * HID + rem] : 0.f;
            float c = sigf(zf) * cprev + sigf(zi) * tanhf(zg);
            g_c1[(size_t)u * B_ * HID + rem] = c;
            g_h1[(size_t)u * B_ * HID + rem] = sigf(zo) * tanhf(c);
        }
        gbar();
    }

    // -------- combine --------
    for (int idx = bid * NTHR + tid; idx < B_ * HGEN; idx += NB * NTHR) {
        int b = idx / HGEN, j = idx % HGEN;
        float lf, rf;
        if (j < HID) {
            lf = g_h1[((size_t)0 * B_ + b) * HID + j];
            rf = g_h1[((size_t)3 * B_ + b) * HID + j];
        } else {
            int jj = j - HID;
            lf = g_h1[((size_t)2 * B_ + b) * HID + jj];
            rf = g_h1[((size_t)1 * B_ + b) * HID + jj];
        }
        float v = 0.5f * (lf + rf);
        g_h0d[idx] = v;
        g_h1d[idx] = v;
    }
}

// ---------------- decoder: persistent, T greedy steps ----------------
__global__ __launch_bounds__(NTHR, 2) void decoder_kernel(
    const float* __restrict__ g0Whh, const float* __restrict__ g0b,
    const float* __restrict__ g1Wih, const float* __restrict__ g1Whh,
    const float* __restrict__ g1b,
    const float* __restrict__ outW, const float* __restrict__ outb,
    float* __restrict__ out, int T)
{
    __shared__ float sA[BKK][BM];
    __shared__ float sB[BKK][BN];
    __shared__ float sH[4][HGEN];
    const int bid = blockIdx.x, tid = threadIdx.x;
    const int mt = bid >> 5, nt = bid & 31;   // 8 x 32 tiles of 128x64 over 1024x2048

    for (int t = 0; t < T; t++) {
        // gen0: z = h0 @ g0Whh^T (token part via table in pw0)
        gemm_tile(g_h0d, HGEN, g0Whh, HGEN, nullptr, 0, nullptr, 0,
                  g_z, 4 * HGEN, mt * BM, nt * BN, sA, sB);
        gbar();
        // pw0
        for (int idx = bid * NTHR + tid; idx < B_ * HGEN; idx += NB * NTHR) {
            int b = idx >> 9, j = idx & (HGEN - 1);
            const float* zr = g_z + (size_t)b * 4 * HGEN;
            const float* tr = g_tabg0 + (size_t)g_tok[b] * 4 * HGEN;
            float zi = zr[j] + tr[j] + g0b[j];
            float zf = zr[HGEN + j] + tr[HGEN + j] + g0b[HGEN + j];
            float zg = zr[2 * HGEN + j] + tr[2 * HGEN + j] + g0b[2 * HGEN + j];
            float zo = zr[3 * HGEN + j] + tr[3 * HGEN + j] + g0b[3 * HGEN + j];
            float c = sigf(zf) * g_c0d[idx] + sigf(zi) * tanhf(zg);
            g_c0d[idx] = c;
            g_h0d[idx] = sigf(zo) * tanhf(c);
        }
        gbar();
        // gen1: z = h0 @ g1Wih^T + h1 @ g1Whh^T
        gemm_tile(g_h0d, HGEN, g1Wih, HGEN, g_h1d, HGEN, g1Whh, HGEN,
                  g_z, 4 * HGEN, mt * BM, nt * BN, sA, sB);
        gbar();
        // pw1 + logits fused: block owns rows bid*4 .. bid*4+3
        for (int r = 0; r < 4; r++) {
            int row = bid * 4 + r;
            const float* zr = g_z + (size_t)row * 4 * HGEN;
            for (int j = tid; j < HGEN; j += NTHR) {
                float zi = zr[j] + g1b[j];
                float zf = zr[HGEN + j] + g1b[HGEN + j];
                float zg = zr[2 * HGEN + j] + g1b[2 * HGEN + j];
                float zo = zr[3 * HGEN + j] + g1b[3 * HGEN + j];
                size_t ix = (size_t)row * HGEN + j;
                float c = sigf(zf) * g_c1d[ix] + sigf(zi) * tanhf(zg);
                g_c1d[ix] = c;
                float h = sigf(zo) * tanhf(c);
                g_h1d[ix] = h;
                sH[r][j] = h;
            }
        }
        __syncthreads();
        {
            int w = tid >> 5, lane = tid & 31;   // 4 warps -> 4 rows
            int row = bid * 4 + w;
            float a0 = 0.f, a1 = 0.f, a2 = 0.f, a3 = 0.f, a4 = 0.f;
            for (int k = lane; k < HGEN; k += 32) {
                float hv = sH[w][k];
                a0 += hv * outW[0 * HGEN + k];
                a1 += hv * outW[1 * HGEN + k];
                a2 += hv * outW[2 * HGEN + k];
                a3 += hv * outW[3 * HGEN + k];
                a4 += hv * outW[4 * HGEN + k];
            }
            #pragma unroll
            for (int off = 16; off; off >>= 1) {
                a0 += __shfl_down_sync(0xffffffffu, a0, off);
                a1 += __shfl_down_sync(0xffffffffu, a1, off);
                a2 += __shfl_down_sync(0xffffffffu, a2, off);
                a3 += __shfl_down_sync(0xffffffffu, a3, off);
                a4 += __shfl_down_sync(0xffffffffu, a4, off);
            }
            if (lane == 0) {
                float L0 = a0 + outb[0], L1 = a1 + outb[1], L2 = a2 + outb[2],
                      L3 = a3 + outb[3], L4 = a4 + outb[4];
                float* op = out + ((size_t)row * T + t) * VOC;
                op[0] = L0; op[1] = L1; op[2] = L2; op[3] = L3; op[4] = L4;
                int bi = 0; float best = L0;                 // first-max = jnp.argmax
                if (L1 > best) { best = L1; bi = 1; }
                if (L2 > best) { best = L2; bi = 2; }
                if (L3 > best) { best = L3; bi = 3; }
                if (L4 > best) { best = L4; bi = 4; }
                g_tok[row] = bi;
            }
        }
        gbar();
    }
}

// ---------------- orchestration: 3 kernel nodes ----------------
extern "C" void kernel_launch(void* const* d_in, const int* in_sizes, int n_in,
                              void* d_out, int out_size) {
    int ei = (in_sizes[2] == 1) ? 3 : 2;
    const int*   leftC  = (const int*)d_in[0];
    const int*   rightC = (const int*)d_in[1];
    const float* emb    = (const float*)d_in[ei + 0];
    const float* c0Wih  = (const float*)d_in[ei + 1];
    const float* c0Whh  = (const float*)d_in[ei + 2];
    const float* c0b    = (const float*)d_in[ei + 3];
    const float* c1Wih  = (const float*)d_in[ei + 4];
    const float* c1Whh  = (const float*)d_in[ei + 5];
    const float* c1b    = (const float*)d_in[ei + 6];
    const float* g0Wih  = (const float*)d_in[ei + 7];
    const float* g0Whh  = (const float*)d_in[ei + 8];
    const float* g0b    = (const float*)d_in[ei + 9];
    const float* g1Wih  = (const float*)d_in[ei + 10];
    const float* g1Whh  = (const float*)d_in[ei + 11];
    const float* g1b    = (const float*)d_in[ei + 12];
    const float* outW   = (const float*)d_in[ei + 13];
    const float* outb   = (const float*)d_in[ei + 14];
    float* out = (float*)d_out;

    const int L = in_sizes[0] / B_;       // 100
    const int T = out_size / (B_ * VOC);  // 256

    setup_kernel<<<512, 256>>>(emb, c0Wih, g0Wih);
    encoder_kernel<<<NB, NTHR>>>(leftC, rightC, c0Whh, c0b, c1Wih, c1Whh, c1b, L);
    decoder_kernel<<<NB, NTHR>>>(g0Whh, g0b, g1Wih, g1Whh, g1b, outW, outb, out, T);
}

// round 5
// speedup vs baseline: 1.0531x; 1.0531x over previous
#include <cuda_runtime.h>
#include <math.h>
#include <stdint.h>

#define B_    1024
#define HID   256
#define HGEN  512
#define VOC   5
#define EMBD  64
#define LMAX  100
#define NB    128     // persistent grid: 128 blocks, 1/SM
#define NTHR  256

// ---------------- static device scratch ----------------
__device__ float g_y0[(size_t)2 * LMAX * B_ * 2 * HID];   // [seq][t][b][512]
__device__ float g_z [(size_t)4 * B_ * 4 * HID * 2];      // gate scratch
__device__ float g_c0[(size_t)4 * B_ * HID];
__device__ float g_h1[(size_t)4 * B_ * HID];
__device__ float g_c1[(size_t)4 * B_ * HID];
__device__ float g_tab0 [2 * VOC * 4 * HID];
__device__ float g_tabg0[VOC * 4 * HGEN];
__device__ float g_h0d[(size_t)B_ * HGEN];
__device__ float g_c0d[(size_t)B_ * HGEN];
__device__ float g_h1d[(size_t)B_ * HGEN];
__device__ float g_c1d[(size_t)B_ * HGEN];
__device__ int   g_tok[B_];

// ---------------- software grid barrier ----------------
__device__ unsigned g_cnt;
__device__ volatile unsigned g_gen;

__device__ __forceinline__ void gbar() {
    __syncthreads();
    __threadfence();
    if (threadIdx.x == 0) {
        unsigned gen = g_gen;
        if (atomicAdd(&g_cnt, 1u) == NB - 1u) {
            g_cnt = 0;
            __threadfence();
            g_gen = gen + 1u;
        } else {
            while (g_gen == gen) { }
        }
        __threadfence();
    }
    __syncthreads();
}

// ---------------- tf32 mma.sync (legacy tensor path, valid on compute_103) ----------------
__device__ __forceinline__ void mma8(float* d, const float4& a, const float2& b) {
    asm volatile(
        "mma.sync.aligned.m16n8k8.row.col.f32.tf32.tf32.f32 "
        "{%0,%1,%2,%3}, {%4,%5,%6,%7}, {%8,%9}, {%0,%1,%2,%3};"
        : "+f"(d[0]), "+f"(d[1]), "+f"(d[2]), "+f"(d[3])
        : "r"(__float_as_uint(a.x)), "r"(__float_as_uint(a.y)),
          "r"(__float_as_uint(a.z)), "r"(__float_as_uint(a.w)),
          "r"(__float_as_uint(b.x)), "r"(__float_as_uint(b.y)));
}

__device__ __forceinline__ void split4(float4 v, float4& h, float4& l) {
    h.x = __uint_as_float(__float_as_uint(v.x) & 0xffffe000u); l.x = v.x - h.x;
    h.y = __uint_as_float(__float_as_uint(v.y) & 0xffffe000u); l.y = v.y - h.y;
    h.z = __uint_as_float(__float_as_uint(v.z) & 0xffffe000u); l.z = v.z - h.z;
    h.w = __uint_as_float(__float_as_uint(v.w) & 0xffffe000u); l.w = v.w - h.w;
}

// ---------------- dynamic smem (floats): A_HI 0, A_LO 4096, B_HI 8192, B_LO 12288, SH 16384 ----------------
#define SMEM_ENC (16384 * 4)
#define SMEM_DEC ((16384 + 8 * HGEN) * 4)

// load one 128x32 k-block of A and W into fragment-ordered hi/lo smem planes
__device__ __forceinline__ void load_kblock(
    const float* __restrict__ A, int lda,
    const float* __restrict__ W, int Kw,
    int rowBase, int colBase, int k0, float* sm)
{
    const int tid = threadIdx.x;
    #pragma unroll
    for (int it = 0; it < 4; it++) {
        int idx = it * NTHR + tid;
        int row = idx >> 3, c4 = idx & 7;
        float4 v = *reinterpret_cast<const float4*>(A + (size_t)(rowBase + row) * lda + k0 + c4 * 4);
        float4 h, l; split4(v, h, l);
        int k8 = c4 >> 1, khalf = c4 & 1, matom = row >> 4, r = row & 15;
        int reg = (r >= 8 ? 1 : 0) + 2 * khalf;
        int base = ((k8 * 8 + matom) * 32 + (r & 7) * 4) * 4 + reg;
        sm[base]      = h.x; sm[base + 4]  = h.y; sm[base + 8]  = h.z; sm[base + 12] = h.w;
        sm[4096 + base]      = l.x; sm[4096 + base + 4]  = l.y;
        sm[4096 + base + 8]  = l.z; sm[4096 + base + 12] = l.w;
    }
    #pragma unroll
    for (int it = 0; it < 4; it++) {
        int idx = it * NTHR + tid;
        int n = idx >> 3, c4 = idx & 7;
        float4 v = *reinterpret_cast<const float4*>(W + (size_t)(colBase + n) * Kw + k0 + c4 * 4);
        float4 h, l; split4(v, h, l);
        int k8 = c4 >> 1, khalf = c4 & 1, natom = n >> 3, nn = n & 7;
        int base = ((k8 * 16 + natom) * 32 + nn * 4) * 2 + khalf;
        sm[8192 + base]     = h.x; sm[8192 + base + 2] = h.y;
        sm[8192 + base + 4] = h.z; sm[8192 + base + 6] = h.w;
        sm[12288 + base]     = l.x; sm[12288 + base + 2] = l.y;
        sm[12288 + base + 4] = l.z; sm[12288 + base + 6] = l.w;
    }
}

// one 128x128 output tile: Z = A0@W0^T (+ A1@W1^T), 3xTF32 split via mma.sync
__device__ void mma_tile(
    const float* __restrict__ A0, int lda0, const float* __restrict__ W0, int K0,
    const float* __restrict__ A1, int lda1, const float* __restrict__ W1, int K1,
    float* __restrict__ Z, int ldz, int rowBase, int colBase, float* sm)
{
    const int tid = threadIdx.x;
    const int w = tid >> 5, lane = tid & 31;
    const int m0 = (w & 3) * 2;          // 2 m-atoms -> rows (w&3)*32
    const int nb0 = (w >> 2) * 8;        // 8 n-atoms -> cols (w>>2)*64

    float acc[2][8][4];
    #pragma unroll
    for (int i = 0; i < 2; i++)
        #pragma unroll
        for (int j = 0; j < 8; j++)
            #pragma unroll
            for (int q = 0; q < 4; q++) acc[i][j][q] = 0.f;

    const int nkb0 = K0 >> 5;
    const int nkb  = nkb0 + (K1 >> 5);

    for (int kb = 0; kb < nkb; kb++) {
        if (kb < nkb0) load_kblock(A0, lda0, W0, K0, rowBase, colBase, kb << 5, sm);
        else           load_kblock(A1, lda1, W1, K1, rowBase, colBase, (kb - nkb0) << 5, sm);
        __syncthreads();

        #pragma unroll
        for (int k8 = 0; k8 < 4; k8++) {
            const float* pa = sm + ((k8 * 8 + m0) * 32 + lane) * 4;
            float4 ah0 = *reinterpret_cast<const float4*>(pa);
            float4 ah1 = *reinterpret_cast<const float4*>(pa + 128);
            float4 al0 = *reinterpret_cast<const float4*>(pa + 4096);
            float4 al1 = *reinterpret_cast<const float4*>(pa + 4096 + 128);
            #pragma unroll
            for (int na = 0; na < 8; na++) {
                const float* pb = sm + 8192 + ((k8 * 16 + nb0 + na) * 32 + lane) * 2;
                float2 bh = *reinterpret_cast<const float2*>(pb);
                float2 bl = *reinterpret_cast<const float2*>(pb + 4096);
                mma8(acc[0][na], ah0, bh);
                mma8(acc[1][na], ah1, bh);
                mma8(acc[0][na], ah0, bl);
                mma8(acc[1][na], ah1, bl);
                mma8(acc[0][na], al0, bh);
                mma8(acc[1][na], al1, bh);
            }
        }
        __syncthreads();
    }

    // epilogue: D fragment -> Z
    #pragma unroll
    for (int i = 0; i < 2; i++) {
        int r0 = rowBase + (m0 + i) * 16 + (lane >> 2);
        #pragma unroll
        for (int na = 0; na < 8; na++) {
            int c0 = colBase + (nb0 + na) * 8 + (lane & 3) * 2;
            *reinterpret_cast<float2*>(Z + (size_t)r0 * ldz + c0) =
                make_float2(acc[i][na][0], acc[i][na][1]);
            *reinterpret_cast<float2*>(Z + (size_t)(r0 + 8) * ldz + c0) =
                make_float2(acc[i][na][2], acc[i][na][3]);
        }
    }
}

__device__ __forceinline__ float sigf(float x) { return 1.f / (1.f + expf(-x)); }

// ---------------- setup: tables + zero state ----------------
__global__ void setup_kernel(const float* __restrict__ emb,
                             const float* __restrict__ c0Wih,
                             const float* __restrict__ g0Wih) {
    int idx = blockIdx.x * blockDim.x + threadIdx.x;
    int stride = gridDim.x * blockDim.x;
    for (int i = idx; i < 4 * B_ * HID; i += stride) { g_c0[i] = 0.f; g_c1[i] = 0.f; }
    for (int i = idx; i < B_ * HGEN; i += stride)    { g_c0d[i] = 0.f; g_c1d[i] = 0.f; }
    for (int i = idx; i < B_; i += stride)           g_tok[i] = 0;

    for (int i = idx; i < 2 * VOC * 4 * HID; i += stride) {
        int n = i % (4 * HID);
        int v = (i / (4 * HID)) % VOC;
        int d = i / (4 * HID * VOC);
        const float* e = emb + v * EMBD;
        const float* w = c0Wih + ((size_t)d * 4 * HID + n) * EMBD;
        float s = 0.f;
        #pragma unroll
        for (int k = 0; k < EMBD; k++) s += e[k] * w[k];
        g_tab0[i] = s;
    }
    for (int i = idx; i < VOC * 4 * HGEN; i += stride) {
        int n = i % (4 * HGEN);
        int v = i / (4 * HGEN);
        const float* e = emb + v * EMBD;
        const float* w = g0Wih + (size_t)n * EMBD;
        float s = 0.f;
        #pragma unroll
        for (int k = 0; k < EMBD; k++) s += e[k] * w[k];
        g_tabg0[i] = s;
    }
}

// ---------------- encoder: persistent ----------------
__global__ __launch_bounds__(NTHR, 1) void encoder_kernel(
    const int* __restrict__ leftC, const int* __restrict__ rightC,
    const float* __restrict__ c0Whh, const float* __restrict__ c0b,
    const float* __restrict__ c1Wih, const float* __restrict__ c1Whh,
    const float* __restrict__ c1b, int L)
{
    extern __shared__ float sm[];
    const int bid = blockIdx.x, tid = threadIdx.x;

    // -------- layer 0: 4 units (seq x dir), L steps --------
    for (int t = 0; t < L; t++) {
        if (t > 0) {
            for (int tile = bid; tile < 256; tile += NB) {
                int u = tile >> 6, rem = tile & 63;
                int mt = rem >> 3, nt = rem & 7;
                int seq = u >> 1, dir = u & 1;
                int time  = dir ? (L - 1 - t) : t;
                int ptime = dir ? (time + 1) : (time - 1);
                const float* A0 = g_y0 + ((size_t)(seq * LMAX + ptime) * B_) * (2 * HID) + dir * HID;
                const float* W0 = c0Whh + (size_t)dir * 4 * HID * HID;
                mma_tile(A0, 2 * HID, W0, HID, nullptr, 0, nullptr, 0,
                         g_z + (size_t)u * B_ * 4 * HID, 4 * HID, mt * 128, nt * 128, sm);
            }
            gbar();
        }
        for (int idx = bid * NTHR + tid; idx < 4 * B_ * HID; idx += NB * NTHR) {
            int u = idx / (B_ * HID), rem = idx % (B_ * HID);
            int b = rem / HID, j = rem % HID;
            int seq = u >> 1, dir = u & 1;
            int time = dir ? (L - 1 - t) : t;
            const int* ctx = seq ? rightC : leftC;
            int v = ctx[b * L + time];
            const float* tr = g_tab0 + ((size_t)dir * VOC + v) * (4 * HID);
            const float* bb = c0b + (size_t)dir * 4 * HID;
            float zi = tr[j] + bb[j];
            float zf = tr[HID + j] + bb[HID + j];
            float zg = tr[2 * HID + j] + bb[2 * HID + j];
            float zo = tr[3 * HID + j] + bb[3 * HID + j];
            float cprev = 0.f;
            if (t > 0) {
                const float* zr = g_z + ((size_t)u * B_ + b) * 4 * HID;
                zi += zr[j]; zf += zr[HID + j]; zg += zr[2 * HID + j]; zo += zr[3 * HID + j];
                cprev = g_c0[(size_t)u * B_ * HID + rem];
            }
            float c = sigf(zf) * cprev + sigf(zi) * tanhf(zg);
            g_c0[(size_t)u * B_ * HID + rem] = c;
            g_y0[((size_t)(seq * LMAX + time) * B_ + b) * (2 * HID) + dir * HID + j] = sigf(zo) * tanhf(c);
        }
        gbar();
    }

    // -------- layer 1: u0=left-fwd(full), u1=right-bwd(full), u2=left-bwd(1), u3=right-fwd(1) --------
    for (int s = 0; s < L; s++) {
        int nu = s ? 2 : 4;
        for (int tile = bid; tile < nu * 64; tile += NB) {
            int u = tile >> 6, rem = tile & 63;
            int mt = rem >> 3, nt = rem & 7;
            int seq = (u == 0 || u == 2) ? 0 : 1;
            int dir = (u == 1 || u == 2) ? 1 : 0;
            int time = dir ? (L - 1 - s) : s;
            const float* A0 = g_y0 + ((size_t)(seq * LMAX + time) * B_) * (2 * HID);
            const float* W0 = c1Wih + (size_t)dir * 4 * HID * 2 * HID;
            const float* A1 = nullptr; const float* W1 = nullptr; int K1 = 0;
            if (s) { A1 = g_h1 + (size_t)u * B_ * HID; W1 = c1Whh + (size_t)dir * 4 * HID * HID; K1 = HID; }
            mma_tile(A0, 2 * HID, W0, 2 * HID, A1, HID, W1, K1,
                     g_z + (size_t)u * B_ * 4 * HID, 4 * HID, mt * 128, nt * 128, sm);
        }
        gbar();
        for (int idx = bid * NTHR + tid; idx < nu * B_ * HID; idx += NB * NTHR) {
            int u = idx / (B_ * HID), rem = idx % (B_ * HID);
            int b = rem / HID, j = rem % HID;
            int dir = (u == 1 || u == 2) ? 1 : 0;
            const float* zr = g_z + ((size_t)u * B_ + b) * 4 * HID;
            const float* bb = c1b + (size_t)dir * 4 * HID;
            float zi = zr[j] + bb[j];
            float zf = zr[HID + j] + bb[HID + j];
            float zg = zr[2 * HID + j] + bb[2 * HID + j];
            float zo = zr[3 * HID + j] + bb[3 * HID + j];
            float cprev = s ? g_c1[(size_t)u * B_ * HID + rem] : 0.f;
            float c = sigf(zf) * cprev + sigf(zi) * tanhf(zg);
            g_c1[(size_t)u * B_ * HID + rem] = c;
            g_h1[(size_t)u * B_ * HID + rem] = sigf(zo) * tanhf(c);
        }
        gbar();
    }

    // -------- combine --------
    for (int idx = bid * NTHR + tid; idx < B_ * HGEN; idx += NB * NTHR) {
        int b = idx / HGEN, j = idx % HGEN;
        float lf, rf;
        if (j < HID) {
            lf = g_h1[((size_t)0 * B_ + b) * HID + j];
            rf = g_h1[((size_t)3 * B_ + b) * HID + j];
        } else {
            int jj = j - HID;
            lf = g_h1[((size_t)2 * B_ + b) * HID + jj];
            rf = g_h1[((size_t)1 * B_ + b) * HID + jj];
        }
        float v = 0.5f * (lf + rf);
        g_h0d[idx] = v;
        g_h1d[idx] = v;
    }
}

// ---------------- decoder: persistent, T greedy steps ----------------
__global__ __launch_bounds__(NTHR, 1) void decoder_kernel(
    const float* __restrict__ g0Whh, const float* __restrict__ g0b,
    const float* __restrict__ g1Wih, const float* __restrict__ g1Whh,
    const float* __restrict__ g1b,
    const float* __restrict__ outW, const float* __restrict__ outb,
    float* __restrict__ out, int T)
{
    extern __shared__ float sm[];
    float* sH = sm + 16384;                         // [8][HGEN]
    const int bid = blockIdx.x, tid = threadIdx.x;
    const int mt = bid >> 4, nt = bid & 15;         // 8 x 16 tiles of 128x128

    for (int t = 0; t < T; t++) {
        // gen0: z = h0 @ g0Whh^T (token part via table in pw0)
        mma_tile(g_h0d, HGEN, g0Whh, HGEN, nullptr, 0, nullptr, 0,
                 g_z, 4 * HGEN, mt * 128, nt * 128, sm);
        gbar();
        // pw0
        for (int idx = bid * NTHR + tid; idx < B_ * HGEN; idx += NB * NTHR) {
            int b = idx >> 9, j = idx & (HGEN - 1);
            const float* zr = g_z + (size_t)b * 4 * HGEN;
            const float* tr = g_tabg0 + (size_t)g_tok[b] * 4 * HGEN;
            float zi = zr[j] + tr[j] + g0b[j];
            float zf = zr[HGEN + j] + tr[HGEN + j] + g0b[HGEN + j];
            float zg = zr[2 * HGEN + j] + tr[2 * HGEN + j] + g0b[2 * HGEN + j];
            float zo = zr[3 * HGEN + j] + tr[3 * HGEN + j] + g0b[3 * HGEN + j];
            float c = sigf(zf) * g_c0d[idx] + sigf(zi) * tanhf(zg);
            g_c0d[idx] = c;
            g_h0d[idx] = sigf(zo) * tanhf(c);
        }
        gbar();
        // gen1: z = h0 @ g1Wih^T + h1 @ g1Whh^T
        mma_tile(g_h0d, HGEN, g1Wih, HGEN, g_h1d, HGEN, g1Whh, HGEN,
                 g_z, 4 * HGEN, mt * 128, nt * 128, sm);
        gbar();
        // pw1: block owns rows bid*8 .. bid*8+7
        for (int r = 0; r < 8; r++) {
            int row = bid * 8 + r;
            const float* zr = g_z + (size_t)row * 4 * HGEN;
            for (int j = tid; j < HGEN; j += NTHR) {
                float zi = zr[j] + g1b[j];
                float zf = zr[HGEN + j] + g1b[HGEN + j];
                float zg = zr[2 * HGEN + j] + g1b[2 * HGEN + j];
                float zo = zr[3 * HGEN + j] + g1b[3 * HGEN + j];
                size_t ix = (size_t)row * HGEN + j;
                float c = sigf(zf) * g_c1d[ix] + sigf(zi) * tanhf(zg);
                g_c1d[ix] = c;
                float h = sigf(zo) * tanhf(c);
                g_h1d[ix] = h;
                sH[r * HGEN + j] = h;
            }
        }
        __syncthreads();
        // logits + argmax: 8 warps, one row each
        {
            int w = tid >> 5, lane = tid & 31;
            int row = bid * 8 + w;
            float a0 = 0.f, a1 = 0.f, a2 = 0.f, a3 = 0.f, a4 = 0.f;
            for (int k = lane; k < HGEN; k += 32) {
                float hv = sH[w * HGEN + k];
                a0 += hv * outW[0 * HGEN + k];
                a1 += hv * outW[1 * HGEN + k];
                a2 += hv * outW[2 * HGEN + k];
                a3 += hv * outW[3 * HGEN + k];
                a4 += hv * outW[4 * HGEN + k];
            }
            #pragma unroll
            for (int off = 16; off; off >>= 1) {
                a0 += __shfl_down_sync(0xffffffffu, a0, off);
                a1 += __shfl_down_sync(0xffffffffu, a1, off);
                a2 += __shfl_down_sync(0xffffffffu, a2, off);
                a3 += __shfl_down_sync(0xffffffffu, a3, off);
                a4 += __shfl_down_sync(0xffffffffu, a4, off);
            }
            if (lane == 0) {
                float L0 = a0 + outb[0], L1 = a1 + outb[1], L2 = a2 + outb[2],
                      L3 = a3 + outb[3], L4 = a4 + outb[4];
                float* op = out + ((size_t)row * T + t) * VOC;
                op[0] = L0; op[1] = L1; op[2] = L2; op[3] = L3; op[4] = L4;
                int bi = 0; float best = L0;                 // first-max = jnp.argmax
                if (L1 > best) { best = L1; bi = 1; }
                if (L2 > best) { best = L2; bi = 2; }
                if (L3 > best) { best = L3; bi = 3; }
                if (L4 > best) { best = L4; bi = 4; }
                g_tok[row] = bi;
            }
        }
        gbar();
    }
}

// ---------------- orchestration: 3 kernel nodes ----------------
extern "C" void kernel_launch(void* const* d_in, const int* in_sizes, int n_in,
                              void* d_out, int out_size) {
    int ei = (in_sizes[2] == 1) ? 3 : 2;
    const int*   leftC  = (const int*)d_in[0];
    const int*   rightC = (const int*)d_in[1];
    const float* emb    = (const float*)d_in[ei + 0];
    const float* c0Wih  = (const float*)d_in[ei + 1];
    const float* c0Whh  = (const float*)d_in[ei + 2];
    const float* c0b    = (const float*)d_in[ei + 3];
    const float* c1Wih  = (const float*)d_in[ei + 4];
    const float* c1Whh  = (const float*)d_in[ei + 5];
    const float* c1b    = (const float*)d_in[ei + 6];
    const float* g0Wih  = (const float*)d_in[ei + 7];
    const float* g0Whh  = (const float*)d_in[ei + 8];
    const float* g0b    = (const float*)d_in[ei + 9];
    const float* g1Wih  = (const float*)d_in[ei + 10];
    const float* g1Whh  = (const float*)d_in[ei + 11];
    const float* g1b    = (const float*)d_in[ei + 12];
    const float* outW   = (const float*)d_in[ei + 13];
    const float* outb   = (const float*)d_in[ei + 14];
    float* out = (float*)d_out;

    const int L = in_sizes[0] / B_;       // 100
    const int T = out_size / (B_ * VOC);  // 256

    cudaFuncSetAttribute(encoder_kernel, cudaFuncAttributeMaxDynamicSharedMemorySize, SMEM_ENC);
    cudaFuncSetAttribute(decoder_kernel, cudaFuncAttributeMaxDynamicSharedMemorySize, SMEM_DEC);

    setup_kernel<<<512, 256>>>(emb, c0Wih, g0Wih);
    encoder_kernel<<<NB, NTHR, SMEM_ENC>>>(leftC, rightC, c0Whh, c0b, c1Wih, c1Whh, c1b, L);
    decoder_kernel<<<NB, NTHR, SMEM_DEC>>>(g0Whh, g0b, g1Wih, g1Whh, g1b, outW, outb, out, T);
}

// round 6
// speedup vs baseline: 2.0020x; 1.9011x over previous
#include <cuda_runtime.h>
#include <cuda_fp16.h>
#include <math.h>
#include <stdint.h>

#define B_    1024
#define HID   256
#define HGEN  512
#define VOC   5
#define EMBD  64
#define LMAX  100
#define NB    128
#define NTHR  256

#define Y0F_MAT 1048576   // halves per y0 frag matrix (1024x512 x 2 planes)

// ---------------- static device scratch ----------------
__device__ __half g_y0f[(size_t)2 * LMAX * Y0F_MAT];      // frag fp16 hi/lo, 400MB
__device__ float  g_z [(size_t)4 * B_ * 4 * HID * 2];     // gate scratch fp32
__device__ float  g_c0[(size_t)4 * B_ * HID];
__device__ float  g_h1[(size_t)4 * B_ * HID];             // L1 h fp32 (combine)
__device__ __half g_h1f[4 * 524288];                      // L1 h frag (1024x256 x2)
__device__ float  g_c1[(size_t)4 * B_ * HID];
__device__ float  g_tab0 [2 * VOC * 4 * HID];
__device__ float  g_tabg0[VOC * 4 * HGEN];
__device__ __half g_h0f [1048576];                        // dec h0 frag (1024x512 x2)
__device__ __half g_h1df[1048576];                        // dec h1 frag
__device__ float  g_c0d[(size_t)B_ * HGEN];
__device__ float  g_c1d[(size_t)B_ * HGEN];
__device__ int    g_tok[B_];
// weight frags (hi plane then lo plane)
__device__ __half g_c0Whhf[2 * 524288];                   // [dir] N=1024 K=256
__device__ __half g_c1Wihf[2 * 1048576];                  // [dir] N=1024 K=512
__device__ __half g_c1Whhf[2 * 524288];                   // [dir] N=1024 K=256
__device__ __half g_g0Whhf[2097152];                      // N=2048 K=512
__device__ __half g_g1Wihf[2097152];
__device__ __half g_g1Whhf[2097152];

// ---------------- software grid barrier ----------------
__device__ unsigned g_cnt;
__device__ volatile unsigned g_gen;

__device__ __forceinline__ void gbar() {
    __syncthreads();
    __threadfence();
    if (threadIdx.x == 0) {
        unsigned gen = g_gen;
        if (atomicAdd(&g_cnt, 1u) == NB - 1u) {
            g_cnt = 0;
            __threadfence();
            g_gen = gen + 1u;
        } else {
            while (g_gen == gen) { }
        }
        __threadfence();
    }
    __syncthreads();
}

// ---------------- frag store helpers ----------------
// A-frag (m16n8k16 row-major A): block(mb,kb) 256 halves; lane=(r%8)*4+((c%8)>>1),
// reg=(r>>3)+2*(c>>3), half=c&1; offset = lane*8 + reg*2 + half.
__device__ __forceinline__ void frag_store(__half* base, int planeHalves, int K16,
                                           int m, int k, float v) {
    int mb = m >> 4, kb = k >> 4, rr = m & 15, cc = k & 15;
    int lane = ((rr & 7) << 2) + ((cc & 7) >> 1);
    int off = ((mb * K16 + kb) << 8) + (lane << 3)
            + (((rr >> 3) + ((cc >> 3) << 1)) << 1) + (cc & 1);
    __half hi = __float2half_rn(v);
    base[off] = hi;
    base[planeHalves + off] = __float2half_rn(v - __half2float(hi));
}

// B-frag (col-major B = W[n][k]): 16n x 16k block; lane=(n%8)*4+((k%8)>>1),
// offset = lane*8 + (n%16>=8)*4 + (k%16>=8)*2 + (k&1).
__device__ __forceinline__ void wfrag_store(__half* base, int planeHalves, int K16,
                                            int n, int k, float v) {
    int nb = n >> 4, kb = k >> 4, nn = n & 15, cc = k & 15;
    int lane = ((nn & 7) << 2) + ((cc & 7) >> 1);
    int off = ((nb * K16 + kb) << 8) + (lane << 3)
            + ((nn >> 3) << 2) + ((cc >> 3) << 1) + (cc & 1);
    __half hi = __float2half_rn(v);
    base[off] = hi;
    base[planeHalves + off] = __float2half_rn(v - __half2float(hi));
}

// ---------------- mma + cp.async primitives ----------------
__device__ __forceinline__ void mma16816(float* d, uint4 a, uint32_t b0, uint32_t b1) {
    asm volatile(
        "mma.sync.aligned.m16n8k16.row.col.f32.f16.f16.f32 "
        "{%0,%1,%2,%3}, {%4,%5,%6,%7}, {%8,%9}, {%0,%1,%2,%3};"
        : "+f"(d[0]), "+f"(d[1]), "+f"(d[2]), "+f"(d[3])
        : "r"(a.x), "r"(a.y), "r"(a.z), "r"(a.w), "r"(b0), "r"(b1));
}
__device__ __forceinline__ void cpa16(uint32_t dst, const void* src) {
    asm volatile("cp.async.cg.shared.global [%0], [%1], 16;" :: "r"(dst), "l"(src));
}
__device__ __forceinline__ uint4 lds128(uint32_t a) {
    uint4 r;
    asm volatile("ld.shared.v4.u32 {%0,%1,%2,%3}, [%4];"
                 : "=r"(r.x), "=r"(r.y), "=r"(r.z), "=r"(r.w) : "r"(a));
    return r;
}
__device__ __forceinline__ uint32_t smem_u32(const void* p) {
    uint32_t a;
    asm("{ .reg .u64 t; cvta.to.shared.u64 t, %1; cvt.u32.u64 %0, t; }" : "=r"(a) : "l"(p));
    return a;
}

// ---------------- pipelined fp16-split GEMM tile (128x128) ----------------
struct GOp {
    const __half* a; int aK16; int aKbOff; int aPlane;
    const __half* w; int wK16; int wPlane;
    int nkb;          // k16 blocks
};

// stage layout: A 16 blocks x 512B (mb0..7 x {hi,lo}), B at +8192 (nb16 j0..7 x {hi,lo})
__device__ __forceinline__ void issue_stage(
    int i, int total, const GOp& o0, const GOp& o1,
    int mtile, int ntile, uint32_t smb, int tid)
{
    if (i < total) {
        const GOp& op = (i < o0.nkb) ? o0 : o1;
        int local = (i < o0.nkb) ? i : i - o0.nkb;
        int akb = op.aKbOff + local;
        uint32_t sbase = smb + (uint32_t)(i & 3) * 16384u;
        #pragma unroll
        for (int c = 0; c < 4; c++) {
            int ch = tid * 4 + c;
            int blk = ch >> 5;
            int off = (ch & 31) << 4;
            const __half* src;
            uint32_t dst;
            if (blk < 16) {
                int mb = mtile * 8 + (blk >> 1);
                int pl = blk & 1;
                src = op.a + (size_t)pl * op.aPlane + ((size_t)(mb * op.aK16 + akb) << 8);
                dst = sbase + blk * 512 + off;
            } else {
                int j = blk - 16;
                int nb = ntile * 8 + (j >> 1);
                int pl = j & 1;
                src = op.w + (size_t)pl * op.wPlane + ((size_t)(nb * op.wK16 + local) << 8);
                dst = sbase + 8192u + j * 512 + off;
            }
            cpa16(dst, (const char*)src + off);
        }
    }
    asm volatile("cp.async.commit_group;" ::: "memory");
}

__device__ void mma_tile(const GOp& o0, const GOp& o1,
                         float* __restrict__ Z, int ldz,
                         int mtile, int ntile, uint32_t smb)
{
    const int tid = threadIdx.x, w = tid >> 5, lane = tid & 31;
    float acc[2][8][4];
    #pragma unroll
    for (int i = 0; i < 2; i++)
        #pragma unroll
        for (int na = 0; na < 8; na++)
            #pragma unroll
            for (int q = 0; q < 4; q++) acc[i][na][q] = 0.f;

    const int total = o0.nkb + o1.nkb;
    issue_stage(0, total, o0, o1, mtile, ntile, smb, tid);
    issue_stage(1, total, o0, o1, mtile, ntile, smb, tid);
    issue_stage(2, total, o0, o1, mtile, ntile, smb, tid);

    const int ma = (w & 3) * 2;          // 2 m-atoms
    const int nj = (w >> 2) * 4;         // 4 n16 blocks -> 8 n-atoms

    for (int k = 0; k < total; k++) {
        asm volatile("cp.async.wait_group 2;" ::: "memory");
        __syncthreads();
        issue_stage(k + 3, total, o0, o1, mtile, ntile, smb, tid);

        uint32_t la = smb + (uint32_t)(k & 3) * 16384u + lane * 16;
        uint4 ah0 = lds128(la + (ma * 2 + 0) * 512);
        uint4 al0 = lds128(la + (ma * 2 + 1) * 512);
        uint4 ah1 = lds128(la + ((ma + 1) * 2 + 0) * 512);
        uint4 al1 = lds128(la + ((ma + 1) * 2 + 1) * 512);
        #pragma unroll
        for (int j = 0; j < 4; j++) {
            uint4 bh = lds128(la + 8192u + ((nj + j) * 2 + 0) * 512);
            uint4 bl = lds128(la + 8192u + ((nj + j) * 2 + 1) * 512);
            int n0 = 2 * j, n1 = 2 * j + 1;
            mma16816(acc[0][n0], ah0, bh.x, bh.y);
            mma16816(acc[0][n0], ah0, bl.x, bl.y);
            mma16816(acc[0][n0], al0, bh.x, bh.y);
            mma16816(acc[1][n0], ah1, bh.x, bh.y);
            mma16816(acc[1][n0], ah1, bl.x, bl.y);
            mma16816(acc[1][n0], al1, bh.x, bh.y);
            mma16816(acc[0][n1], ah0, bh.z, bh.w);
            mma16816(acc[0][n1], ah0, bl.z, bl.w);
            mma16816(acc[0][n1], al0, bh.z, bh.w);
            mma16816(acc[1][n1], ah1, bh.z, bh.w);
            mma16816(acc[1][n1], ah1, bl.z, bl.w);
            mma16816(acc[1][n1], al1, bh.z, bh.w);
        }
    }

    const int nab = (w >> 2) * 8;
    #pragma unroll
    for (int i = 0; i < 2; i++) {
        int r0 = mtile * 128 + (ma + i) * 16 + (lane >> 2);
        #pragma unroll
        for (int na = 0; na < 8; na++) {
            int c0 = ntile * 128 + (nab + na) * 8 + (lane & 3) * 2;
            *reinterpret_cast<float2*>(Z + (size_t)r0 * ldz + c0) =
                make_float2(acc[i][na][0], acc[i][na][1]);
            *reinterpret_cast<float2*>(Z + (size_t)(r0 + 8) * ldz + c0) =
                make_float2(acc[i][na][2], acc[i][na][3]);
        }
    }
}

__device__ __forceinline__ float sigf(float x) { return 1.f / (1.f + expf(-x)); }

// ---------------- setup: tables + weight frags + zero state ----------------
__global__ void setup_kernel(const float* __restrict__ emb,
                             const float* __restrict__ c0Wih,
                             const float* __restrict__ c0Whh,
                             const float* __restrict__ c1Wih,
                             const float* __restrict__ c1Whh,
                             const float* __restrict__ g0Wih,
                             const float* __restrict__ g0Whh,
                             const float* __restrict__ g1Wih,
                             const float* __restrict__ g1Whh) {
    int idx = blockIdx.x * blockDim.x + threadIdx.x;
    int stride = gridDim.x * blockDim.x;
    for (int i = idx; i < 4 * B_ * HID; i += stride) { g_c0[i] = 0.f; g_c1[i] = 0.f; }
    for (int i = idx; i < B_ * HGEN; i += stride)    { g_c0d[i] = 0.f; g_c1d[i] = 0.f; }
    for (int i = idx; i < B_; i += stride)           g_tok[i] = 0;

    for (int i = idx; i < 2 * VOC * 4 * HID; i += stride) {
        int n = i % (4 * HID);
        int v = (i / (4 * HID)) % VOC;
        int d = i / (4 * HID * VOC);
        const float* e = emb + v * EMBD;
        const float* ww = c0Wih + ((size_t)d * 4 * HID + n) * EMBD;
        float s = 0.f;
        #pragma unroll
        for (int k = 0; k < EMBD; k++) s += e[k] * ww[k];
        g_tab0[i] = s;
    }
    for (int i = idx; i < VOC * 4 * HGEN; i += stride) {
        int n = i % (4 * HGEN);
        int v = i / (4 * HGEN);
        const float* e = emb + v * EMBD;
        const float* ww = g0Wih + (size_t)n * EMBD;
        float s = 0.f;
        #pragma unroll
        for (int k = 0; k < EMBD; k++) s += e[k] * ww[k];
        g_tabg0[i] = s;
    }

    // weight frag conversions
    for (int i = idx; i < 2 * 1024 * 256; i += stride) {
        int d = i / (1024 * 256), r = i % (1024 * 256);
        wfrag_store(g_c0Whhf + d * 524288, 262144, 16, r / 256, r % 256, c0Whh[i]);
    }
    for (int i = idx; i < 2 * 1024 * 512; i += stride) {
        int d = i / (1024 * 512), r = i % (1024 * 512);
        wfrag_store(g_c1Wihf + d * 1048576, 524288, 32, r / 512, r % 512, c1Wih[i]);
    }
    for (int i = idx; i < 2 * 1024 * 256; i += stride) {
        int d = i / (1024 * 256), r = i % (1024 * 256);
        wfrag_store(g_c1Whhf + d * 524288, 262144, 16, r / 256, r % 256, c1Whh[i]);
    }
    for (int i = idx; i < 2048 * 512; i += stride)
        wfrag_store(g_g0Whhf, 1048576, 32, i / 512, i % 512, g0Whh[i]);
    for (int i = idx; i < 2048 * 512; i += stride)
        wfrag_store(g_g1Wihf, 1048576, 32, i / 512, i % 512, g1Wih[i]);
    for (int i = idx; i < 2048 * 512; i += stride)
        wfrag_store(g_g1Whhf, 1048576, 32, i / 512, i % 512, g1Whh[i]);
}

// ---------------- encoder ----------------
__global__ __launch_bounds__(NTHR, 1) void encoder_kernel(
    const int* __restrict__ leftC, const int* __restrict__ rightC,
    const float* __restrict__ c0b, const float* __restrict__ c1b, int L)
{
    extern __shared__ char sm[];
    const uint32_t smb = smem_u32(sm);
    const int bid = blockIdx.x, tid = threadIdx.x;

    // -------- layer 0 --------
    for (int t = 0; t < L; t++) {
        if (t > 0) {
            for (int tile = bid; tile < 256; tile += NB) {
                int u = tile >> 6, rem = tile & 63;
                int mt = rem >> 3, nt = rem & 7;
                int seq = u >> 1, dir = u & 1;
                int time  = dir ? (L - 1 - t) : t;
                int ptime = dir ? (time + 1) : (time - 1);
                GOp o0 = { g_y0f + (size_t)(seq * LMAX + ptime) * Y0F_MAT, 32, dir * 16, 524288,
                           g_c0Whhf + dir * 524288, 16, 262144, 16 };
                GOp o1 = { nullptr, 0, 0, 0, nullptr, 0, 0, 0 };
                mma_tile(o0, o1, g_z + (size_t)u * B_ * 4 * HID, 4 * HID, mt, nt, smb);
            }
            gbar();
        }
        for (int idx = bid * NTHR + tid; idx < 4 * B_ * HID; idx += NB * NTHR) {
            int u = idx / (B_ * HID), rem = idx % (B_ * HID);
            int b = rem / HID, j = rem % HID;
            int seq = u >> 1, dir = u & 1;
            int time = dir ? (L - 1 - t) : t;
            const int* ctx = seq ? rightC : leftC;
            int v = ctx[b * L + time];
            const float* tr = g_tab0 + ((size_t)dir * VOC + v) * (4 * HID);
            const float* bb = c0b + (size_t)dir * 4 * HID;
            float zi = tr[j] + bb[j];
            float zf = tr[HID + j] + bb[HID + j];
            float zg = tr[2 * HID + j] + bb[2 * HID + j];
            float zo = tr[3 * HID + j] + bb[3 * HID + j];
            float cprev = 0.f;
            if (t > 0) {
                const float* zr = g_z + ((size_t)u * B_ + b) * 4 * HID;
                zi += zr[j]; zf += zr[HID + j]; zg += zr[2 * HID + j]; zo += zr[3 * HID + j];
                cprev = g_c0[(size_t)u * B_ * HID + rem];
            }
            float c = sigf(zf) * cprev + sigf(zi) * tanhf(zg);
            g_c0[(size_t)u * B_ * HID + rem] = c;
            float h = sigf(zo) * tanhf(c);
            frag_store(g_y0f + (size_t)(seq * LMAX + time) * Y0F_MAT, 524288, 32,
                       b, dir * HID + j, h);
        }
        gbar();
    }

    // -------- layer 1 --------
    for (int s = 0; s < L; s++) {
        int nu = s ? 2 : 4;
        for (int tile = bid; tile < nu * 64; tile += NB) {
            int u = tile >> 6, rem = tile & 63;
            int mt = rem >> 3, nt = rem & 7;
            int seq = (u == 0 || u == 2) ? 0 : 1;
            int dir = (u == 1 || u == 2) ? 1 : 0;
            int time = dir ? (L - 1 - s) : s;
            GOp o0 = { g_y0f + (size_t)(seq * LMAX + time) * Y0F_MAT, 32, 0, 524288,
                       g_c1Wihf + dir * 1048576, 32, 524288, 32 };
            GOp o1 = { g_h1f + u * 524288, 16, 0, 262144,
                       g_c1Whhf + dir * 524288, 16, 262144, s ? 16 : 0 };
            mma_tile(o0, o1, g_z + (size_t)u * B_ * 4 * HID, 4 * HID, mt, nt, smb);
        }
        gbar();
        for (int idx = bid * NTHR + tid; idx < nu * B_ * HID; idx += NB * NTHR) {
            int u = idx / (B_ * HID), rem = idx % (B_ * HID);
            int b = rem / HID, j = rem % HID;
            int dir = (u == 1 || u == 2) ? 1 : 0;
            const float* zr = g_z + ((size_t)u * B_ + b) * 4 * HID;
            const float* bb = c1b + (size_t)dir * 4 * HID;
            float zi = zr[j] + bb[j];
            float zf = zr[HID + j] + bb[HID + j];
            float zg = zr[2 * HID + j] + bb[2 * HID + j];
            float zo = zr[3 * HID + j] + bb[3 * HID + j];
            float cprev = s ? g_c1[(size_t)u * B_ * HID + rem] : 0.f;
            float c = sigf(zf) * cprev + sigf(zi) * tanhf(zg);
            g_c1[(size_t)u * B_ * HID + rem] = c;
            float h = sigf(zo) * tanhf(c);
            g_h1[(size_t)u * B_ * HID + rem] = h;
            frag_store(g_h1f + u * 524288, 262144, 16, b, j, h);
        }
        gbar();
    }

    // -------- combine -> decoder initial h (frag) --------
    for (int idx = bid * NTHR + tid; idx < B_ * HGEN; idx += NB * NTHR) {
        int b = idx / HGEN, j = idx % HGEN;
        float lf, rf;
        if (j < HID) {
            lf = g_h1[((size_t)0 * B_ + b) * HID + j];
            rf = g_h1[((size_t)3 * B_ + b) * HID + j];
        } else {
            int jj = j - HID;
            lf = g_h1[((size_t)2 * B_ + b) * HID + jj];
            rf = g_h1[((size_t)1 * B_ + b) * HID + jj];
        }
        float v = 0.5f * (lf + rf);
        frag_store(g_h0f,  524288, 32, b, j, v);
        frag_store(g_h1df, 524288, 32, b, j, v);
    }
}

// ---------------- decoder ----------------
__global__ __launch_bounds__(NTHR, 1) void decoder_kernel(
    const float* __restrict__ g0b, const float* __restrict__ g1b,
    const float* __restrict__ outW, const float* __restrict__ outb,
    float* __restrict__ out, int T)
{
    extern __shared__ char sm[];
    const uint32_t smb = smem_u32(sm);
    float* sH = reinterpret_cast<float*>(sm + 65536);     // [8][HGEN]
    const int bid = blockIdx.x, tid = threadIdx.x;
    const int mt = bid >> 4, nt = bid & 15;

    for (int t = 0; t < T; t++) {
        {   // gen0: z = h0 @ g0Whh^T
            GOp o0 = { g_h0f, 32, 0, 524288, g_g0Whhf, 32, 1048576, 32 };
            GOp o1 = { nullptr, 0, 0, 0, nullptr, 0, 0, 0 };
            mma_tile(o0, o1, g_z, 4 * HGEN, mt, nt, smb);
        }
        gbar();
        for (int idx = bid * NTHR + tid; idx < B_ * HGEN; idx += NB * NTHR) {
            int b = idx >> 9, j = idx & (HGEN - 1);
            const float* zr = g_z + (size_t)b * 4 * HGEN;
            const float* tr = g_tabg0 + (size_t)g_tok[b] * 4 * HGEN;
            float zi = zr[j] + tr[j] + g0b[j];
            float zf = zr[HGEN + j] + tr[HGEN + j] + g0b[HGEN + j];
            float zg = zr[2 * HGEN + j] + tr[2 * HGEN + j] + g0b[2 * HGEN + j];
            float zo = zr[3 * HGEN + j] + tr[3 * HGEN + j] + g0b[3 * HGEN + j];
            float c = sigf(zf) * g_c0d[idx] + sigf(zi) * tanhf(zg);
            g_c0d[idx] = c;
            frag_store(g_h0f, 524288, 32, b, j, sigf(zo) * tanhf(c));
        }
        gbar();
        {   // gen1: z = h0 @ g1Wih^T + h1 @ g1Whh^T
            GOp o0 = { g_h0f,  32, 0, 524288, g_g1Wihf, 32, 1048576, 32 };
            GOp o1 = { g_h1df, 32, 0, 524288, g_g1Whhf, 32, 1048576, 32 };
            mma_tile(o0, o1, g_z, 4 * HGEN, mt, nt, smb);
        }
        gbar();
        for (int r = 0; r < 8; r++) {
            int row = bid * 8 + r;
            const float* zr = g_z + (size_t)row * 4 * HGEN;
            for (int j = tid; j < HGEN; j += NTHR) {
                float zi = zr[j] + g1b[j];
                float zf = zr[HGEN + j] + g1b[HGEN + j];
                float zg = zr[2 * HGEN + j] + g1b[2 * HGEN + j];
                float zo = zr[3 * HGEN + j] + g1b[3 * HGEN + j];
                size_t ix = (size_t)row * HGEN + j;
                float c = sigf(zf) * g_c1d[ix] + sigf(zi) * tanhf(zg);
                g_c1d[ix] = c;
                float h = sigf(zo) * tanhf(c);
                frag_store(g_h1df, 524288, 32, row, j, h);
                sH[r * HGEN + j] = h;
            }
        }
        __syncthreads();
        {
            int w = tid >> 5, lane = tid & 31;
            int row = bid * 8 + w;
            float a0 = 0.f, a1 = 0.f, a2 = 0.f, a3 = 0.f, a4 = 0.f;
            for (int k = lane; k < HGEN; k += 32) {
                float hv = sH[w * HGEN + k];
                a0 += hv * outW[0 * HGEN + k];
                a1 += hv * outW[1 * HGEN + k];
                a2 += hv * outW[2 * HGEN + k];
                a3 += hv * outW[3 * HGEN + k];
                a4 += hv * outW[4 * HGEN + k];
            }
            #pragma unroll
            for (int off = 16; off; off >>= 1) {
                a0 += __shfl_down_sync(0xffffffffu, a0, off);
                a1 += __shfl_down_sync(0xffffffffu, a1, off);
                a2 += __shfl_down_sync(0xffffffffu, a2, off);
                a3 += __shfl_down_sync(0xffffffffu, a3, off);
                a4 += __shfl_down_sync(0xffffffffu, a4, off);
            }
            if (lane == 0) {
                float L0 = a0 + outb[0], L1 = a1 + outb[1], L2 = a2 + outb[2],
                      L3 = a3 + outb[3], L4 = a4 + outb[4];
                float* op = out + ((size_t)row * T + t) * VOC;
                op[0] = L0; op[1] = L1; op[2] = L2; op[3] = L3; op[4] = L4;
                int bi = 0; float best = L0;
                if (L1 > best) { best = L1; bi = 1; }
                if (L2 > best) { best = L2; bi = 2; }
                if (L3 > best) { best = L3; bi = 3; }
                if (L4 > best) { best = L4; bi = 4; }
                g_tok[row] = bi;
            }
        }
        gbar();
    }
}

// ---------------- orchestration ----------------
extern "C" void kernel_launch(void* const* d_in, const int* in_sizes, int n_in,
                              void* d_out, int out_size) {
    int ei = (in_sizes[2] == 1) ? 3 : 2;
    const int*   leftC  = (const int*)d_in[0];
    const int*   rightC = (const int*)d_in[1];
    const float* emb    = (const float*)d_in[ei + 0];
    const float* c0Wih  = (const float*)d_in[ei + 1];
    const float* c0Whh  = (const float*)d_in[ei + 2];
    const float* c0b    = (const float*)d_in[ei + 3];
    const float* c1Wih  = (const float*)d_in[ei + 4];
    const float* c1Whh  = (const float*)d_in[ei + 5];
    const float* c1b    = (const float*)d_in[ei + 6];
    const float* g0Wih  = (const float*)d_in[ei + 7];
    const float* g0Whh  = (const float*)d_in[ei + 8];
    const float* g0b    = (const float*)d_in[ei + 9];
    const float* g1Wih  = (const float*)d_in[ei + 10];
    const float* g1Whh  = (const float*)d_in[ei + 11];
    const float* g1b    = (const float*)d_in[ei + 12];
    const float* outW   = (const float*)d_in[ei + 13];
    const float* outb   = (const float*)d_in[ei + 14];
    float* out = (float*)d_out;

    const int L = in_sizes[0] / B_;       // 100
    const int T = out_size / (B_ * VOC);  // 256

    cudaFuncSetAttribute(encoder_kernel, cudaFuncAttributeMaxDynamicSharedMemorySize, 65536);
    cudaFuncSetAttribute(decoder_kernel, cudaFuncAttributeMaxDynamicSharedMemorySize, 81920);

    setup_kernel<<<512, 256>>>(emb, c0Wih, c0Whh, c1Wih, c1Whh, g0Wih, g0Whh, g1Wih, g1Whh);
    encoder_kernel<<<NB, NTHR, 65536>>>(leftC, rightC, c0b, c1b, L);
    decoder_kernel<<<NB, NTHR, 81920>>>(g0b, g1b, outW, outb, out, T);
}

// round 7
// speedup vs baseline: 2.5474x; 1.2724x over previous
#include <cuda_runtime.h>
#include <cuda_fp16.h>
#include <math.h>
#include <stdint.h>

#define B_    1024
#define HID   256
#define HGEN  512
#define VOC   5
#define EMBD  64
#define LMAX  100
#define NB    128
#define NTHR  256

#define Y0F_MAT 1048576   // halves per y0 frag matrix (64 mb x 32 kb x 512)

// ---------------- static device scratch (frag layouts: [kb][mb][hi256|lo256]) ----------------
__device__ __align__(16) __half g_y0f[(size_t)2 * LMAX * Y0F_MAT];
__device__ float  g_z [(size_t)4 * B_ * 4 * HID * 2];
__device__ float  g_c0[(size_t)4 * B_ * HID];
__device__ float  g_h1[(size_t)4 * B_ * HID];
__device__ __align__(16) __half g_h1f[4 * 524288];        // [u] 16kb x 64mb x 512
__device__ float  g_c1[(size_t)4 * B_ * HID];
__device__ float  g_tab0 [2 * VOC * 4 * HID];             // bias folded in
__device__ float  g_tabg0[VOC * 4 * HGEN];                // bias folded in
__device__ __align__(16) __half g_h0f [1048576];          // 32kb x 64mb x 512
__device__ __align__(16) __half g_h1df[1048576];
__device__ float  g_c0d[(size_t)B_ * HGEN];
__device__ float  g_c1d[(size_t)B_ * HGEN];
__device__ int    g_tok[B_];
// weight frags [kb][nb][hi256|lo256]
__device__ __align__(16) __half g_c0Whhf[2 * 524288];     // [dir] 16kb x 64nb
__device__ __align__(16) __half g_c1Wihf[2 * 1048576];    // [dir] 32kb x 64nb
__device__ __align__(16) __half g_c1Whhf[2 * 524288];     // [dir] 16kb x 64nb
__device__ __align__(16) __half g_g0Whhf[2097152];        // 32kb x 128nb
__device__ __align__(16) __half g_g1Wihf[2097152];
__device__ __align__(16) __half g_g1Whhf[2097152];

// ---------------- software grid barrier ----------------
__device__ unsigned g_cnt;
__device__ volatile unsigned g_gen;

__device__ __forceinline__ void gbar() {
    __syncthreads();
    __threadfence();
    if (threadIdx.x == 0) {
        unsigned gen = g_gen;
        if (atomicAdd(&g_cnt, 1u) == NB - 1u) {
            g_cnt = 0;
            __threadfence();
            g_gen = gen + 1u;
        } else {
            while (g_gen == gen) { }
        }
        __threadfence();
    }
    __syncthreads();
}

// ---------------- frag store helpers ----------------
__device__ __forceinline__ void frag_store(__half* base, int m, int k, float v) {
    int mb = m >> 4, kb = k >> 4, rr = m & 15, cc = k & 15;
    int lane = ((rr & 7) << 2) + ((cc & 7) >> 1);
    int intra = (lane << 3) + (((rr >> 3) + ((cc >> 3) << 1)) << 1) + (cc & 1);
    size_t off = ((size_t)(kb * 64 + mb) << 9) + intra;
    __half hi = __float2half_rn(v);
    base[off] = hi;
    base[off + 256] = __float2half_rn(v - __half2float(hi));
}

__device__ __forceinline__ void wfrag_store(__half* base, int NBc, int n, int k, float v) {
    int nb = n >> 4, kb = k >> 4, nn = n & 15, cc = k & 15;
    int lane = ((nn & 7) << 2) + ((cc & 7) >> 1);
    int intra = (lane << 3) + ((nn >> 3) << 2) + ((cc >> 3) << 1) + (cc & 1);
    size_t off = ((size_t)(kb * NBc + nb) << 9) + intra;
    __half hi = __float2half_rn(v);
    base[off] = hi;
    base[off + 256] = __float2half_rn(v - __half2float(hi));
}

// ---------------- primitives ----------------
__device__ __forceinline__ void mma16816(float* d, uint4 a, uint32_t b0, uint32_t b1) {
    asm volatile(
        "mma.sync.aligned.m16n8k16.row.col.f32.f16.f16.f32 "
        "{%0,%1,%2,%3}, {%4,%5,%6,%7}, {%8,%9}, {%0,%1,%2,%3};"
        : "+f"(d[0]), "+f"(d[1]), "+f"(d[2]), "+f"(d[3])
        : "r"(a.x), "r"(a.y), "r"(a.z), "r"(a.w), "r"(b0), "r"(b1));
}
__device__ __forceinline__ uint4 lds128(uint32_t a) {
    uint4 r;
    asm volatile("ld.shared.v4.u32 {%0,%1,%2,%3}, [%4];"
                 : "=r"(r.x), "=r"(r.y), "=r"(r.z), "=r"(r.w) : "r"(a));
    return r;
}
__device__ __forceinline__ uint32_t smem_u32(const void* p) {
    uint32_t a;
    asm("{ .reg .u64 t; cvta.to.shared.u64 t, %1; cvt.u32.u64 %0, t; }" : "=r"(a) : "l"(p));
    return a;
}
__device__ __forceinline__ void bulk_cp(uint32_t dst, const void* src, uint32_t mbar) {
    asm volatile(
        "cp.async.bulk.shared::cta.global.mbarrier::complete_tx::bytes [%0], [%1], 8192, [%2];"
        :: "r"(dst), "l"(src), "r"(mbar) : "memory");
}
__device__ __forceinline__ void waitp(uint32_t mbar, int phase) {
    asm volatile(
        "{\n\t"
        ".reg .pred P1;\n\t"
        "WAIT_LOOP_%=:\n\t"
        "mbarrier.try_wait.parity.acquire.cta.shared::cta.b64 P1, [%0], %1, 0x989680;\n\t"
        "@P1 bra.uni WAIT_DONE_%=;\n\t"
        "bra.uni WAIT_LOOP_%=;\n\t"
        "WAIT_DONE_%=:\n\t"
        "}"
        :: "r"(mbar), "r"(phase) : "memory");
}

// smem: [0..31] 4 mbarriers, [1024 .. 1024+64K) 4 stages x (A 8K | B 8K), then sH
#define OFF_MBAR  0
#define OFF_TILES 1024
#define OFF_SH    (OFF_TILES + 65536)
#define SMEM_ENC  (OFF_TILES + 65536)
#define SMEM_DEC  (OFF_SH + 8 * HGEN * 4)

struct GOp {
    const __half* a; int aKbOff;
    const __half* w; int wNB;
    int nkb;
};

__device__ __forceinline__ void issue_stage(
    int sg, int k, const GOp& o0, const GOp& o1,
    int mtile, int ntile, uint32_t smb, int tid)
{
    if (tid != 0) return;
    const GOp& op = (k < o0.nkb) ? o0 : o1;
    int local = (k < o0.nkb) ? k : k - o0.nkb;
    int akb = op.aKbOff + local;
    uint32_t sbase = smb + OFF_TILES + (uint32_t)(sg & 3) * 16384u;
    uint32_t mbar = smb + OFF_MBAR + (uint32_t)(sg & 3) * 8u;
    asm volatile("mbarrier.arrive.expect_tx.shared.b64 _, [%0], %1;"
                 :: "r"(mbar), "r"(16384u) : "memory");
    const __half* asrc = op.a + ((size_t)(akb * 64 + mtile * 8) << 9);
    const __half* wsrc = op.w + ((size_t)(local * op.wNB + ntile * 8) << 9);
    bulk_cp(sbase, asrc, mbar);
    bulk_cp(sbase + 8192u, wsrc, mbar);
}

__device__ void mma_tile(const GOp& o0, const GOp& o1,
                         float* __restrict__ Z, int ldz,
                         int mtile, int ntile, uint32_t smb, int& cnt)
{
    const int tid = threadIdx.x, w = tid >> 5, lane = tid & 31;
    float acc[2][8][4];
    #pragma unroll
    for (int i = 0; i < 2; i++)
        #pragma unroll
        for (int na = 0; na < 8; na++)
            #pragma unroll
            for (int q = 0; q < 4; q++) acc[i][na][q] = 0.f;

    const int total = o0.nkb + o1.nkb;
    issue_stage(cnt + 0, 0, o0, o1, mtile, ntile, smb, tid);
    issue_stage(cnt + 1, 1, o0, o1, mtile, ntile, smb, tid);
    issue_stage(cnt + 2, 2, o0, o1, mtile, ntile, smb, tid);

    const int ma = (w & 3) * 2;
    const int nj = (w >> 2) * 4;

    for (int k = 0; k < total; k++) {
        int sg = cnt + k;
        waitp(smb + OFF_MBAR + (uint32_t)(sg & 3) * 8u, (sg >> 2) & 1);

        uint32_t la = smb + OFF_TILES + (uint32_t)(sg & 3) * 16384u + lane * 16;
        uint4 ah0 = lds128(la + (ma + 0) * 1024);
        uint4 al0 = lds128(la + (ma + 0) * 1024 + 512);
        uint4 ah1 = lds128(la + (ma + 1) * 1024);
        uint4 al1 = lds128(la + (ma + 1) * 1024 + 512);
        #pragma unroll
        for (int j = 0; j < 4; j++) {
            uint4 bh = lds128(la + 8192u + (nj + j) * 1024);
            uint4 bl = lds128(la + 8192u + (nj + j) * 1024 + 512);
            int n0 = 2 * j, n1 = 2 * j + 1;
            mma16816(acc[0][n0], ah0, bh.x, bh.y);
            mma16816(acc[0][n0], ah0, bl.x, bl.y);
            mma16816(acc[0][n0], al0, bh.x, bh.y);
            mma16816(acc[1][n0], ah1, bh.x, bh.y);
            mma16816(acc[1][n0], ah1, bl.x, bl.y);
            mma16816(acc[1][n0], al1, bh.x, bh.y);
            mma16816(acc[0][n1], ah0, bh.z, bh.w);
            mma16816(acc[0][n1], ah0, bl.z, bl.w);
            mma16816(acc[0][n1], al0, bh.z, bh.w);
            mma16816(acc[1][n1], ah1, bh.z, bh.w);
            mma16816(acc[1][n1], ah1, bl.z, bl.w);
            mma16816(acc[1][n1], al1, bh.z, bh.w);
        }
        __syncthreads();
        if (k + 3 < total)
            issue_stage(cnt + k + 3, k + 3, o0, o1, mtile, ntile, smb, tid);
    }
    cnt += total;

    const int nab = (w >> 2) * 8;
    #pragma unroll
    for (int i = 0; i < 2; i++) {
        int r0 = mtile * 128 + (ma + i) * 16 + (lane >> 2);
        #pragma unroll
        for (int na = 0; na < 8; na++) {
            int c0 = ntile * 128 + (nab + na) * 8 + (lane & 3) * 2;
            *reinterpret_cast<float2*>(Z + (size_t)r0 * ldz + c0) =
                make_float2(acc[i][na][0], acc[i][na][1]);
            *reinterpret_cast<float2*>(Z + (size_t)(r0 + 8) * ldz + c0) =
                make_float2(acc[i][na][2], acc[i][na][3]);
        }
    }
}

__device__ __forceinline__ void pipe_init(uint32_t smb) {
    if (threadIdx.x == 0) {
        #pragma unroll
        for (int s = 0; s < 4; s++)
            asm volatile("mbarrier.init.shared.b64 [%0], 1;"
                         :: "r"(smb + OFF_MBAR + s * 8u) : "memory");
    }
    __syncthreads();
}

__device__ __forceinline__ float sigf(float x) { return 1.f / (1.f + expf(-x)); }

// ---------------- setup: tables(+bias) + weight frags + zero state ----------------
__global__ void setup_kernel(const float* __restrict__ emb,
                             const float* __restrict__ c0Wih,
                             const float* __restrict__ c0Whh,
                             const float* __restrict__ c0b,
                             const float* __restrict__ c1Wih,
                             const float* __restrict__ c1Whh,
                             const float* __restrict__ g0Wih,
                             const float* __restrict__ g0Whh,
                             const float* __restrict__ g0b,
                             const float* __restrict__ g1Wih,
                             const float* __restrict__ g1Whh) {
    int idx = blockIdx.x * blockDim.x + threadIdx.x;
    int stride = gridDim.x * blockDim.x;
    for (int i = idx; i < 4 * B_ * HID; i += stride) { g_c0[i] = 0.f; g_c1[i] = 0.f; }
    for (int i = idx; i < B_ * HGEN; i += stride)    { g_c0d[i] = 0.f; g_c1d[i] = 0.f; }
    for (int i = idx; i < B_; i += stride)           g_tok[i] = 0;

    for (int i = idx; i < 2 * VOC * 4 * HID; i += stride) {
        int n = i % (4 * HID);
        int v = (i / (4 * HID)) % VOC;
        int d = i / (4 * HID * VOC);
        const float* e = emb + v * EMBD;
        const float* ww = c0Wih + ((size_t)d * 4 * HID + n) * EMBD;
        float s = 0.f;
        #pragma unroll
        for (int k = 0; k < EMBD; k++) s += e[k] * ww[k];
        g_tab0[i] = s + c0b[d * 4 * HID + n];
    }
    for (int i = idx; i < VOC * 4 * HGEN; i += stride) {
        int n = i % (4 * HGEN);
        int v = i / (4 * HGEN);
        const float* e = emb + v * EMBD;
        const float* ww = g0Wih + (size_t)n * EMBD;
        float s = 0.f;
        #pragma unroll
        for (int k = 0; k < EMBD; k++) s += e[k] * ww[k];
        g_tabg0[i] = s + g0b[n];
    }

    for (int i = idx; i < 2 * 1024 * 256; i += stride) {
        int d = i / (1024 * 256), r = i % (1024 * 256);
        wfrag_store(g_c0Whhf + d * 524288, 64, r / 256, r % 256, c0Whh[i]);
    }
    for (int i = idx; i < 2 * 1024 * 512; i += stride) {
        int d = i / (1024 * 512), r = i % (1024 * 512);
        wfrag_store(g_c1Wihf + d * 1048576, 64, r / 512, r % 512, c1Wih[i]);
    }
    for (int i = idx; i < 2 * 1024 * 256; i += stride) {
        int d = i / (1024 * 256), r = i % (1024 * 256);
        wfrag_store(g_c1Whhf + d * 524288, 64, r / 256, r % 256, c1Whh[i]);
    }
    for (int i = idx; i < 2048 * 512; i += stride)
        wfrag_store(g_g0Whhf, 128, i / 512, i % 512, g0Whh[i]);
    for (int i = idx; i < 2048 * 512; i += stride)
        wfrag_store(g_g1Wihf, 128, i / 512, i % 512, g1Wih[i]);
    for (int i = idx; i < 2048 * 512; i += stride)
        wfrag_store(g_g1Whhf, 128, i / 512, i % 512, g1Whh[i]);
}

// ---------------- encoder ----------------
__global__ __launch_bounds__(NTHR, 1) void encoder_kernel(
    const int* __restrict__ leftC, const int* __restrict__ rightC,
    const float* __restrict__ c1b, int L)
{
    extern __shared__ char sm[];
    const uint32_t smb = smem_u32(sm);
    const int bid = blockIdx.x, tid = threadIdx.x;
    pipe_init(smb);
    int cnt = 0;

    // -------- layer 0 --------
    for (int t = 0; t < L; t++) {
        if (t > 0) {
            for (int tile = bid; tile < 256; tile += NB) {
                int u = tile >> 6, rem = tile & 63;
                int mt = rem >> 3, nt = rem & 7;
                int seq = u >> 1, dir = u & 1;
                int time  = dir ? (L - 1 - t) : t;
                int ptime = dir ? (time + 1) : (time - 1);
                GOp o0 = { g_y0f + (size_t)(seq * LMAX + ptime) * Y0F_MAT, dir * 16,
                           g_c0Whhf + dir * 524288, 64, 16 };
                GOp o1 = { nullptr, 0, nullptr, 0, 0 };
                mma_tile(o0, o1, g_z + (size_t)u * B_ * 4 * HID, 4 * HID, mt, nt, smb, cnt);
            }
            gbar();
        }
        for (int idx = bid * NTHR + tid; idx < 4 * B_ * HID; idx += NB * NTHR) {
            int u = idx / (B_ * HID), rem = idx % (B_ * HID);
            int b = rem / HID, j = rem % HID;
            int seq = u >> 1, dir = u & 1;
            int time = dir ? (L - 1 - t) : t;
            const int* ctx = seq ? rightC : leftC;
            int v = ctx[b * L + time];
            const float* tr = g_tab0 + ((size_t)dir * VOC + v) * (4 * HID);
            float zi = tr[j];
            float zf = tr[HID + j];
            float zg = tr[2 * HID + j];
            float zo = tr[3 * HID + j];
            float cprev = 0.f;
            if (t > 0) {
                const float* zr = g_z + ((size_t)u * B_ + b) * 4 * HID;
                zi += zr[j]; zf += zr[HID + j]; zg += zr[2 * HID + j]; zo += zr[3 * HID + j];
                cprev = g_c0[(size_t)u * B_ * HID + rem];
            }
            float c = sigf(zf) * cprev + sigf(zi) * tanhf(zg);
            g_c0[(size_t)u * B_ * HID + rem] = c;
            float h = sigf(zo) * tanhf(c);
            frag_store(g_y0f + (size_t)(seq * LMAX + time) * Y0F_MAT, b, dir * HID + j, h);
        }
        gbar();
    }

    // -------- layer 1 --------
    for (int s = 0; s < L; s++) {
        int nu = s ? 2 : 4;
        for (int tile = bid; tile < nu * 64; tile += NB) {
            int u = tile >> 6, rem = tile & 63;
            int mt = rem >> 3, nt = rem & 7;
            int seq = (u == 0 || u == 2) ? 0 : 1;
            int dir = (u == 1 || u == 2) ? 1 : 0;
            int time = dir ? (L - 1 - s) : s;
            GOp o0 = { g_y0f + (size_t)(seq * LMAX + time) * Y0F_MAT, 0,
                       g_c1Wihf + dir * 1048576, 64, 32 };
            GOp o1 = { g_h1f + u * 524288, 0,
                       g_c1Whhf + dir * 524288, 64, s ? 16 : 0 };
            mma_tile(o0, o1, g_z + (size_t)u * B_ * 4 * HID, 4 * HID, mt, nt, smb, cnt);
        }
        gbar();
        for (int idx = bid * NTHR + tid; idx < nu * B_ * HID; idx += NB * NTHR) {
            int u = idx / (B_ * HID), rem = idx % (B_ * HID);
            int b = rem / HID, j = rem % HID;
            int dir = (u == 1 || u == 2) ? 1 : 0;
            const float* zr = g_z + ((size_t)u * B_ + b) * 4 * HID;
            const float* bb = c1b + (size_t)dir * 4 * HID;
            float zi = zr[j] + bb[j];
            float zf = zr[HID + j] + bb[HID + j];
            float zg = zr[2 * HID + j] + bb[2 * HID + j];
            float zo = zr[3 * HID + j] + bb[3 * HID + j];
            float cprev = s ? g_c1[(size_t)u * B_ * HID + rem] : 0.f;
            float c = sigf(zf) * cprev + sigf(zi) * tanhf(zg);
            g_c1[(size_t)u * B_ * HID + rem] = c;
            float h = sigf(zo) * tanhf(c);
            g_h1[(size_t)u * B_ * HID + rem] = h;
            frag_store(g_h1f + u * 524288, b, j, h);
        }
        gbar();
    }

    // -------- combine -> decoder initial h (frag) --------
    for (int idx = bid * NTHR + tid; idx < B_ * HGEN; idx += NB * NTHR) {
        int b = idx / HGEN, j = idx % HGEN;
        float lf, rf;
        if (j < HID) {
            lf = g_h1[((size_t)0 * B_ + b) * HID + j];
            rf = g_h1[((size_t)3 * B_ + b) * HID + j];
        } else {
            int jj = j - HID;
            lf = g_h1[((size_t)2 * B_ + b) * HID + jj];
            rf = g_h1[((size_t)1 * B_ + b) * HID + jj];
        }
        float v = 0.5f * (lf + rf);
        frag_store(g_h0f,  b, j, v);
        frag_store(g_h1df, b, j, v);
    }
}

// ---------------- decoder ----------------
__global__ __launch_bounds__(NTHR, 1) void decoder_kernel(
    const float* __restrict__ g1b,
    const float* __restrict__ outW, const float* __restrict__ outb,
    float* __restrict__ out, int T)
{
    extern __shared__ char sm[];
    const uint32_t smb = smem_u32(sm);
    float* sH = reinterpret_cast<float*>(sm + OFF_SH);
    const int bid = blockIdx.x, tid = threadIdx.x;
    const int mt = bid >> 4, nt = bid & 15;
    pipe_init(smb);
    int cnt = 0;

    for (int t = 0; t < T; t++) {
        {   // gen0: z = h0 @ g0Whh^T
            GOp o0 = { g_h0f, 0, g_g0Whhf, 128, 32 };
            GOp o1 = { nullptr, 0, nullptr, 0, 0 };
            mma_tile(o0, o1, g_z, 4 * HGEN, mt, nt, smb, cnt);
        }
        gbar();
        for (int idx = bid * NTHR + tid; idx < B_ * HGEN; idx += NB * NTHR) {
            int b = idx >> 9, j = idx & (HGEN - 1);
            const float* zr = g_z + (size_t)b * 4 * HGEN;
            const float* tr = g_tabg0 + (size_t)g_tok[b] * 4 * HGEN;
            float zi = zr[j] + tr[j];
            float zf = zr[HGEN + j] + tr[HGEN + j];
            float zg = zr[2 * HGEN + j] + tr[2 * HGEN + j];
            float zo = zr[3 * HGEN + j] + tr[3 * HGEN + j];
            float c = sigf(zf) * g_c0d[idx] + sigf(zi) * tanhf(zg);
            g_c0d[idx] = c;
            frag_store(g_h0f, b, j, sigf(zo) * tanhf(c));
        }
        gbar();
        {   // gen1: z = h0 @ g1Wih^T + h1 @ g1Whh^T
            GOp o0 = { g_h0f,  0, g_g1Wihf, 128, 32 };
            GOp o1 = { g_h1df, 0, g_g1Whhf, 128, 32 };
            mma_tile(o0, o1, g_z, 4 * HGEN, mt, nt, smb, cnt);
        }
        gbar();
        for (int r = 0; r < 8; r++) {
            int row = bid * 8 + r;
            const float* zr = g_z + (size_t)row * 4 * HGEN;
            for (int j = tid; j < HGEN; j += NTHR) {
                float zi = zr[j] + g1b[j];
                float zf = zr[HGEN + j] + g1b[HGEN + j];
                float zg = zr[2 * HGEN + j] + g1b[2 * HGEN + j];
                float zo = zr[3 * HGEN + j] + g1b[3 * HGEN + j];
                size_t ix = (size_t)row * HGEN + j;
                float c = sigf(zf) * g_c1d[ix] + sigf(zi) * tanhf(zg);
                g_c1d[ix] = c;
                float h = sigf(zo) * tanhf(c);
                frag_store(g_h1df, row, j, h);
                sH[r * HGEN + j] = h;
            }
        }
        __syncthreads();
        {
            int w = tid >> 5, lane = tid & 31;
            int row = bid * 8 + w;
            float a0 = 0.f, a1 = 0.f, a2 = 0.f, a3 = 0.f, a4 = 0.f;
            for (int k = lane; k < HGEN; k += 32) {
                float hv = sH[w * HGEN + k];
                a0 += hv * outW[0 * HGEN + k];
                a1 += hv * outW[1 * HGEN + k];
                a2 += hv * outW[2 * HGEN + k];
                a3 += hv * outW[3 * HGEN + k];
                a4 += hv * outW[4 * HGEN + k];
            }
            #pragma unroll
            for (int off = 16; off; off >>= 1) {
                a0 += __shfl_down_sync(0xffffffffu, a0, off);
                a1 += __shfl_down_sync(0xffffffffu, a1, off);
                a2 += __shfl_down_sync(0xffffffffu, a2, off);
                a3 += __shfl_down_sync(0xffffffffu, a3, off);
                a4 += __shfl_down_sync(0xffffffffu, a4, off);
            }
            if (lane == 0) {
                float L0 = a0 + outb[0], L1 = a1 + outb[1], L2 = a2 + outb[2],
                      L3 = a3 + outb[3], L4 = a4 + outb[4];
                float* op = out + ((size_t)row * T + t) * VOC;
                op[0] = L0; op[1] = L1; op[2] = L2; op[3] = L3; op[4] = L4;
                int bi = 0; float best = L0;
                if (L1 > best) { best = L1; bi = 1; }
                if (L2 > best) { best = L2; bi = 2; }
                if (L3 > best) { best = L3; bi = 3; }
                if (L4 > best) { best = L4; bi = 4; }
                g_tok[row] = bi;
            }
        }
        gbar();
    }
}

// ---------------- orchestration ----------------
extern "C" void kernel_launch(void* const* d_in, const int* in_sizes, int n_in,
                              void* d_out, int out_size) {
    int ei = (in_sizes[2] == 1) ? 3 : 2;
    const int*   leftC  = (const int*)d_in[0];
    const int*   rightC = (const int*)d_in[1];
    const float* emb    = (const float*)d_in[ei + 0];
    const float* c0Wih  = (const float*)d_in[ei + 1];
    const float* c0Whh  = (const float*)d_in[ei + 2];
    const float* c0b    = (const float*)d_in[ei + 3];
    const float* c1Wih  = (const float*)d_in[ei + 4];
    const float* c1Whh  = (const float*)d_in[ei + 5];
    const float* c1b    = (const float*)d_in[ei + 6];
    const float* g0Wih  = (const float*)d_in[ei + 7];
    const float* g0Whh  = (const float*)d_in[ei + 8];
    const float* g0b    = (const float*)d_in[ei + 9];
    const float* g1Wih  = (const float*)d_in[ei + 10];
    const float* g1Whh  = (const float*)d_in[ei + 11];
    const float* g1b    = (const float*)d_in[ei + 12];
    const float* outW   = (const float*)d_in[ei + 13];
    const float* outb   = (const float*)d_in[ei + 14];
    float* out = (float*)d_out;

    const int L = in_sizes[0] / B_;       // 100
    const int T = out_size / (B_ * VOC);  // 256

    cudaFuncSetAttribute(encoder_kernel, cudaFuncAttributeMaxDynamicSharedMemorySize, SMEM_ENC);
    cudaFuncSetAttribute(decoder_kernel, cudaFuncAttributeMaxDynamicSharedMemorySize, SMEM_DEC);

    setup_kernel<<<512, 256>>>(emb, c0Wih, c0Whh, c0b, c1Wih, c1Whh,
                               g0Wih, g0Whh, g0b, g1Wih, g1Whh);
    encoder_kernel<<<NB, NTHR, SMEM_ENC>>>(leftC, rightC, c1b, L);
    decoder_kernel<<<NB, NTHR, SMEM_DEC>>>(g1b, outW, outb, out, T);
}

// round 8
// speedup vs baseline: 2.7177x; 1.0669x over previous
#include <cuda_runtime.h>
#include <cuda_fp16.h>
#include <math.h>
#include <stdint.h>

#define B_    1024
#define HID   256
#define HGEN  512
#define VOC   5
#define EMBD  64
#define LMAX  100
#define NB    128
#define NTHR  256

#define Y0F_MAT 1048576   // halves per y0 frag matrix (32 kb x 64 mb x 512)

// ---------------- static device scratch (frag layouts: [kb][mb][hi256|lo256]) ----------------
__device__ __align__(16) __half g_y0f[(size_t)2 * LMAX * Y0F_MAT];
__device__ float  g_z [(size_t)4 * B_ * 4 * HID * 2];
__device__ float  g_c0[(size_t)4 * B_ * HID];
__device__ float  g_h1[(size_t)4 * B_ * HID];
__device__ __align__(16) __half g_h1f[4 * 524288];        // [u] 16kb x 64mb x 512
__device__ float  g_c1[(size_t)4 * B_ * HID];
__device__ float  g_tab0 [2 * VOC * 4 * HID];             // bias folded in
__device__ float  g_tabg0[VOC * 4 * HGEN];                // bias folded in
__device__ __align__(16) __half g_h0f [1048576];          // 32kb x 64mb x 512
__device__ __align__(16) __half g_h1df[1048576];
__device__ float  g_c0d[(size_t)B_ * HGEN];
__device__ float  g_c1d[(size_t)B_ * HGEN];
__device__ int    g_tok[B_];
// weight frags [kb][nb][hi256|lo256]
__device__ __align__(16) __half g_c0Whhf[2 * 524288];     // [dir] 16kb x 64nb
__device__ __align__(16) __half g_c1Wihf[2 * 1048576];    // [dir] 32kb x 64nb
__device__ __align__(16) __half g_c1Whhf[2 * 524288];     // [dir] 16kb x 64nb
__device__ __align__(16) __half g_g0Whhf[2097152];        // 32kb x 128nb
__device__ __align__(16) __half g_g1Wihf[2097152];
__device__ __align__(16) __half g_g1Whhf[2097152];

// ---------------- software grid barrier ----------------
__device__ unsigned g_cnt;
__device__ volatile unsigned g_gen;

__device__ __forceinline__ void gbar() {
    __syncthreads();
    __threadfence();
    if (threadIdx.x == 0) {
        unsigned gen = g_gen;
        if (atomicAdd(&g_cnt, 1u) == NB - 1u) {
            g_cnt = 0;
            __threadfence();
            g_gen = gen + 1u;
        } else {
            while (g_gen == gen) { }
        }
        __threadfence();
    }
    __syncthreads();
}

// ---------------- frag store helpers ----------------
__device__ __forceinline__ void frag_store(__half* base, int m, int k, float v) {
    int mb = m >> 4, kb = k >> 4, rr = m & 15, cc = k & 15;
    int lane = ((rr & 7) << 2) + ((cc & 7) >> 1);
    int intra = (lane << 3) + (((rr >> 3) + ((cc >> 3) << 1)) << 1) + (cc & 1);
    size_t off = ((size_t)(kb * 64 + mb) << 9) + intra;
    __half hi = __float2half_rn(v);
    base[off] = hi;
    base[off + 256] = __float2half_rn(v - __half2float(hi));
}

__device__ __forceinline__ void wfrag_store(__half* base, int NBc, int n, int k, float v) {
    int nb = n >> 4, kb = k >> 4, nn = n & 15, cc = k & 15;
    int lane = ((nn & 7) << 2) + ((cc & 7) >> 1);
    int intra = (lane << 3) + ((nn >> 3) << 2) + ((cc >> 3) << 1) + (cc & 1);
    size_t off = ((size_t)(kb * NBc + nb) << 9) + intra;
    __half hi = __float2half_rn(v);
    base[off] = hi;
    base[off + 256] = __float2half_rn(v - __half2float(hi));
}

// ---------------- primitives ----------------
__device__ __forceinline__ void mma16816(float* d, uint4 a, uint32_t b0, uint32_t b1) {
    asm volatile(
        "mma.sync.aligned.m16n8k16.row.col.f32.f16.f16.f32 "
        "{%0,%1,%2,%3}, {%4,%5,%6,%7}, {%8,%9}, {%0,%1,%2,%3};"
        : "+f"(d[0]), "+f"(d[1]), "+f"(d[2]), "+f"(d[3])
        : "r"(a.x), "r"(a.y), "r"(a.z), "r"(a.w), "r"(b0), "r"(b1));
}
__device__ __forceinline__ uint4 lds128(uint32_t a) {
    uint4 r;
    asm volatile("ld.shared.v4.u32 {%0,%1,%2,%3}, [%4];"
                 : "=r"(r.x), "=r"(r.y), "=r"(r.z), "=r"(r.w) : "r"(a));
    return r;
}
__device__ __forceinline__ uint32_t smem_u32(const void* p) {
    uint32_t a;
    asm("{ .reg .u64 t; cvta.to.shared.u64 t, %1; cvt.u32.u64 %0, t; }" : "=r"(a) : "l"(p));
    return a;
}
__device__ __forceinline__ void bulk_cp(uint32_t dst, const void* src, uint32_t mbar) {
    asm volatile(
        "cp.async.bulk.shared::cta.global.mbarrier::complete_tx::bytes [%0], [%1], 8192, [%2];"
        :: "r"(dst), "l"(src), "r"(mbar) : "memory");
}
__device__ __forceinline__ void waitp(uint32_t mbar, int phase) {
    asm volatile(
        "{\n\t"
        ".reg .pred P1;\n\t"
        "WAIT_LOOP_%=:\n\t"
        "mbarrier.try_wait.parity.acquire.cta.shared::cta.b64 P1, [%0], %1, 0x989680;\n\t"
        "@P1 bra.uni WAIT_DONE_%=;\n\t"
        "bra.uni WAIT_LOOP_%=;\n\t"
        "WAIT_DONE_%=:\n\t"
        "}"
        :: "r"(mbar), "r"(phase) : "memory");
}

// smem: [0..31] 4 mbarriers; [1024 ..) 4 stages x 32KB:
//   stage: A(k16 sub0) 8K | A(sub1) 8K | B(sub0) 8K | B(sub1) 8K ; then sH
#define OFF_MBAR  0
#define OFF_TILES 1024
#define OFF_SH    (OFF_TILES + 131072)
#define SMEM_ENC  (OFF_TILES + 131072)
#define SMEM_DEC  (OFF_SH + 8 * HGEN * 4)

struct GOp {
    const __half* a; int aKbOff;
    const __half* w; int wNB;
    int nkb;          // k16 blocks (always even)
};

// stage st covers k16 blocks 2*st, 2*st+1 (never straddles ops: all nkb even)
__device__ __forceinline__ void issue_stage(
    int sg, int st, const GOp& o0, const GOp& o1,
    int mtile, int ntile, uint32_t smb, int tid)
{
    if (tid != 0) return;
    int k0 = 2 * st;
    const GOp& op = (k0 < o0.nkb) ? o0 : o1;
    int local0 = (k0 < o0.nkb) ? k0 : k0 - o0.nkb;
    uint32_t sbase = smb + OFF_TILES + (uint32_t)(sg & 3) * 32768u;
    uint32_t mbar = smb + OFF_MBAR + (uint32_t)(sg & 3) * 8u;
    asm volatile("mbarrier.arrive.expect_tx.shared.b64 _, [%0], %1;"
                 :: "r"(mbar), "r"(32768u) : "memory");
    #pragma unroll
    for (int q = 0; q < 2; q++) {
        int local = local0 + q;
        int akb = op.aKbOff + local;
        const __half* asrc = op.a + ((size_t)(akb * 64 + mtile * 8) << 9);
        const __half* wsrc = op.w + ((size_t)(local * op.wNB + ntile * 8) << 9);
        bulk_cp(sbase + q * 8192u, asrc, mbar);
        bulk_cp(sbase + 16384u + q * 8192u, wsrc, mbar);
    }
}

__device__ void mma_tile(const GOp& o0, const GOp& o1,
                         float* __restrict__ Z, int ldz,
                         int mtile, int ntile, uint32_t smb, int& cnt)
{
    const int tid = threadIdx.x, w = tid >> 5, lane = tid & 31;
    float acc[2][8][4];
    #pragma unroll
    for (int i = 0; i < 2; i++)
        #pragma unroll
        for (int na = 0; na < 8; na++)
            #pragma unroll
            for (int q = 0; q < 4; q++) acc[i][na][q] = 0.f;

    const int nstages = (o0.nkb + o1.nkb) >> 1;
    issue_stage(cnt + 0, 0, o0, o1, mtile, ntile, smb, tid);
    issue_stage(cnt + 1, 1, o0, o1, mtile, ntile, smb, tid);
    issue_stage(cnt + 2, 2, o0, o1, mtile, ntile, smb, tid);

    const int ma = (w & 3) * 2;
    const int nj = (w >> 2) * 4;

    for (int st = 0; st < nstages; st++) {
        int sg = cnt + st;
        waitp(smb + OFF_MBAR + (uint32_t)(sg & 3) * 8u, (sg >> 2) & 1);
        uint32_t sbase = smb + OFF_TILES + (uint32_t)(sg & 3) * 32768u + lane * 16;

        #pragma unroll
        for (int q = 0; q < 2; q++) {
            uint32_t laA = sbase + q * 8192u;
            uint32_t laB = sbase + 16384u + q * 8192u;
            uint4 ah0 = lds128(laA + (ma + 0) * 1024);
            uint4 al0 = lds128(laA + (ma + 0) * 1024 + 512);
            uint4 ah1 = lds128(laA + (ma + 1) * 1024);
            uint4 al1 = lds128(laA + (ma + 1) * 1024 + 512);
            uint4 bh[4], bl[4];
            #pragma unroll
            for (int j = 0; j < 4; j++) {
                bh[j] = lds128(laB + (nj + j) * 1024);
                bl[j] = lds128(laB + (nj + j) * 1024 + 512);
            }
            // pass 1: hi x hi — each accumulator touched once per pass
            #pragma unroll
            for (int j = 0; j < 4; j++) {
                mma16816(acc[0][2*j],   ah0, bh[j].x, bh[j].y);
                mma16816(acc[1][2*j],   ah1, bh[j].x, bh[j].y);
                mma16816(acc[0][2*j+1], ah0, bh[j].z, bh[j].w);
                mma16816(acc[1][2*j+1], ah1, bh[j].z, bh[j].w);
            }
            // pass 2: hi x lo
            #pragma unroll
            for (int j = 0; j < 4; j++) {
                mma16816(acc[0][2*j],   ah0, bl[j].x, bl[j].y);
                mma16816(acc[1][2*j],   ah1, bl[j].x, bl[j].y);
                mma16816(acc[0][2*j+1], ah0, bl[j].z, bl[j].w);
                mma16816(acc[1][2*j+1], ah1, bl[j].z, bl[j].w);
            }
            // pass 3: lo x hi
            #pragma unroll
            for (int j = 0; j < 4; j++) {
                mma16816(acc[0][2*j],   al0, bh[j].x, bh[j].y);
                mma16816(acc[1][2*j],   al1, bh[j].x, bh[j].y);
                mma16816(acc[0][2*j+1], al0, bh[j].z, bh[j].w);
                mma16816(acc[1][2*j+1], al1, bh[j].z, bh[j].w);
            }
        }
        __syncthreads();
        if (st + 3 < nstages)
            issue_stage(cnt + st + 3, st + 3, o0, o1, mtile, ntile, smb, tid);
    }
    cnt += nstages;

    const int nab = (w >> 2) * 8;
    #pragma unroll
    for (int i = 0; i < 2; i++) {
        int r0 = mtile * 128 + (ma + i) * 16 + (lane >> 2);
        #pragma unroll
        for (int na = 0; na < 8; na++) {
            int c0 = ntile * 128 + (nab + na) * 8 + (lane & 3) * 2;
            *reinterpret_cast<float2*>(Z + (size_t)r0 * ldz + c0) =
                make_float2(acc[i][na][0], acc[i][na][1]);
            *reinterpret_cast<float2*>(Z + (size_t)(r0 + 8) * ldz + c0) =
                make_float2(acc[i][na][2], acc[i][na][3]);
        }
    }
}

__device__ __forceinline__ void pipe_init(uint32_t smb) {
    if (threadIdx.x == 0) {
        #pragma unroll
        for (int s = 0; s < 4; s++)
            asm volatile("mbarrier.init.shared.b64 [%0], 1;"
                         :: "r"(smb + OFF_MBAR + s * 8u) : "memory");
    }
    __syncthreads();
}

__device__ __forceinline__ float sigf(float x) { return 1.f / (1.f + expf(-x)); }

// ---------------- setup ----------------
__global__ void setup_kernel(const float* __restrict__ emb,
                             const float* __restrict__ c0Wih,
                             const float* __restrict__ c0Whh,
                             const float* __restrict__ c0b,
                             const float* __restrict__ c1Wih,
                             const float* __restrict__ c1Whh,
                             const float* __restrict__ g0Wih,
                             const float* __restrict__ g0Whh,
                             const float* __restrict__ g0b,
                             const float* __restrict__ g1Wih,
                             const float* __restrict__ g1Whh) {
    int idx = blockIdx.x * blockDim.x + threadIdx.x;
    int stride = gridDim.x * blockDim.x;
    for (int i = idx; i < 4 * B_ * HID; i += stride) { g_c0[i] = 0.f; g_c1[i] = 0.f; }
    for (int i = idx; i < B_ * HGEN; i += stride)    { g_c0d[i] = 0.f; g_c1d[i] = 0.f; }
    for (int i = idx; i < B_; i += stride)           g_tok[i] = 0;

    for (int i = idx; i < 2 * VOC * 4 * HID; i += stride) {
        int n = i % (4 * HID);
        int v = (i / (4 * HID)) % VOC;
        int d = i / (4 * HID * VOC);
        const float* e = emb + v * EMBD;
        const float* ww = c0Wih + ((size_t)d * 4 * HID + n) * EMBD;
        float s = 0.f;
        #pragma unroll
        for (int k = 0; k < EMBD; k++) s += e[k] * ww[k];
        g_tab0[i] = s + c0b[d * 4 * HID + n];
    }
    for (int i = idx; i < VOC * 4 * HGEN; i += stride) {
        int n = i % (4 * HGEN);
        int v = i / (4 * HGEN);
        const float* e = emb + v * EMBD;
        const float* ww = g0Wih + (size_t)n * EMBD;
        float s = 0.f;
        #pragma unroll
        for (int k = 0; k < EMBD; k++) s += e[k] * ww[k];
        g_tabg0[i] = s + g0b[n];
    }

    for (int i = idx; i < 2 * 1024 * 256; i += stride) {
        int d = i / (1024 * 256), r = i % (1024 * 256);
        wfrag_store(g_c0Whhf + d * 524288, 64, r / 256, r % 256, c0Whh[i]);
    }
    for (int i = idx; i < 2 * 1024 * 512; i += stride) {
        int d = i / (1024 * 512), r = i % (1024 * 512);
        wfrag_store(g_c1Wihf + d * 1048576, 64, r / 512, r % 512, c1Wih[i]);
    }
    for (int i = idx; i < 2 * 1024 * 256; i += stride) {
        int d = i / (1024 * 256), r = i % (1024 * 256);
        wfrag_store(g_c1Whhf + d * 524288, 64, r / 256, r % 256, c1Whh[i]);
    }
    for (int i = idx; i < 2048 * 512; i += stride)
        wfrag_store(g_g0Whhf, 128, i / 512, i % 512, g0Whh[i]);
    for (int i = idx; i < 2048 * 512; i += stride)
        wfrag_store(g_g1Wihf, 128, i / 512, i % 512, g1Wih[i]);
    for (int i = idx; i < 2048 * 512; i += stride)
        wfrag_store(g_g1Whhf, 128, i / 512, i % 512, g1Whh[i]);
}

// ---------------- encoder ----------------
__global__ __launch_bounds__(NTHR, 1) void encoder_kernel(
    const int* __restrict__ leftC, const int* __restrict__ rightC,
    const float* __restrict__ c1b, int L)
{
    extern __shared__ char sm[];
    const uint32_t smb = smem_u32(sm);
    const int bid = blockIdx.x, tid = threadIdx.x;
    pipe_init(smb);
    int cnt = 0;

    // -------- layer 0 --------
    for (int t = 0; t < L; t++) {
        if (t > 0) {
            for (int tile = bid; tile < 256; tile += NB) {
                int u = tile >> 6, rem = tile & 63;
                int mt = rem >> 3, nt = rem & 7;
                int seq = u >> 1, dir = u & 1;
                int time  = dir ? (L - 1 - t) : t;
                int ptime = dir ? (time + 1) : (time - 1);
                GOp o0 = { g_y0f + (size_t)(seq * LMAX + ptime) * Y0F_MAT, dir * 16,
                           g_c0Whhf + dir * 524288, 64, 16 };
                GOp o1 = { nullptr, 0, nullptr, 0, 0 };
                mma_tile(o0, o1, g_z + (size_t)u * B_ * 4 * HID, 4 * HID, mt, nt, smb, cnt);
            }
            gbar();
        }
        for (int idx = bid * NTHR + tid; idx < 4 * B_ * HID; idx += NB * NTHR) {
            int u = idx / (B_ * HID), rem = idx % (B_ * HID);
            int b = rem / HID, j = rem % HID;
            int seq = u >> 1, dir = u & 1;
            int time = dir ? (L - 1 - t) : t;
            const int* ctx = seq ? rightC : leftC;
            int v = ctx[b * L + time];
            const float* tr = g_tab0 + ((size_t)dir * VOC + v) * (4 * HID);
            float zi = tr[j];
            float zf = tr[HID + j];
            float zg = tr[2 * HID + j];
            float zo = tr[3 * HID + j];
            float cprev = 0.f;
            if (t > 0) {
                const float* zr = g_z + ((size_t)u * B_ + b) * 4 * HID;
                zi += zr[j]; zf += zr[HID + j]; zg += zr[2 * HID + j]; zo += zr[3 * HID + j];
                cprev = g_c0[(size_t)u * B_ * HID + rem];
            }
            float c = sigf(zf) * cprev + sigf(zi) * tanhf(zg);
            g_c0[(size_t)u * B_ * HID + rem] = c;
            float h = sigf(zo) * tanhf(c);
            frag_store(g_y0f + (size_t)(seq * LMAX + time) * Y0F_MAT, b, dir * HID + j, h);
        }
        gbar();
    }

    // -------- layer 1 --------
    for (int s = 0; s < L; s++) {
        int nu = s ? 2 : 4;
        for (int tile = bid; tile < nu * 64; tile += NB) {
            int u = tile >> 6, rem = tile & 63;
            int mt = rem >> 3, nt = rem & 7;
            int seq = (u == 0 || u == 2) ? 0 : 1;
            int dir = (u == 1 || u == 2) ? 1 : 0;
            int time = dir ? (L - 1 - s) : s;
            GOp o0 = { g_y0f + (size_t)(seq * LMAX + time) * Y0F_MAT, 0,
                       g_c1Wihf + dir * 1048576, 64, 32 };
            GOp o1 = { g_h1f + u * 524288, 0,
                       g_c1Whhf + dir * 524288, 64, s ? 16 : 0 };
            mma_tile(o0, o1, g_z + (size_t)u * B_ * 4 * HID, 4 * HID, mt, nt, smb, cnt);
        }
        gbar();
        for (int idx = bid * NTHR + tid; idx < nu * B_ * HID; idx += NB * NTHR) {
            int u = idx / (B_ * HID), rem = idx % (B_ * HID);
            int b = rem / HID, j = rem % HID;
            int dir = (u == 1 || u == 2) ? 1 : 0;
            const float* zr = g_z + ((size_t)u * B_ + b) * 4 * HID;
            const float* bb = c1b + (size_t)dir * 4 * HID;
            float zi = zr[j] + bb[j];
            float zf = zr[HID + j] + bb[HID + j];
            float zg = zr[2 * HID + j] + bb[2 * HID + j];
            float zo = zr[3 * HID + j] + bb[3 * HID + j];
            float cprev = s ? g_c1[(size_t)u * B_ * HID + rem] : 0.f;
            float c = sigf(zf) * cprev + sigf(zi) * tanhf(zg);
            g_c1[(size_t)u * B_ * HID + rem] = c;
            float h = sigf(zo) * tanhf(c);
            g_h1[(size_t)u * B_ * HID + rem] = h;
            frag_store(g_h1f + u * 524288, b, j, h);
        }
        gbar();
    }

    // -------- combine -> decoder initial h (frag) --------
    for (int idx = bid * NTHR + tid; idx < B_ * HGEN; idx += NB * NTHR) {
        int b = idx / HGEN, j = idx % HGEN;
        float lf, rf;
        if (j < HID) {
            lf = g_h1[((size_t)0 * B_ + b) * HID + j];
            rf = g_h1[((size_t)3 * B_ + b) * HID + j];
        } else {
            int jj = j - HID;
            lf = g_h1[((size_t)2 * B_ + b) * HID + jj];
            rf = g_h1[((size_t)1 * B_ + b) * HID + jj];
        }
        float v = 0.5f * (lf + rf);
        frag_store(g_h0f,  b, j, v);
        frag_store(g_h1df, b, j, v);
    }
}

// ---------------- decoder ----------------
__global__ __launch_bounds__(NTHR, 1) void decoder_kernel(
    const float* __restrict__ g1b,
    const float* __restrict__ outW, const float* __restrict__ outb,
    float* __restrict__ out, int T)
{
    extern __shared__ char sm[];
    const uint32_t smb = smem_u32(sm);
    float* sH = reinterpret_cast<float*>(sm + OFF_SH);
    const int bid = blockIdx.x, tid = threadIdx.x;
    const int mt = bid >> 4, nt = bid & 15;
    pipe_init(smb);
    int cnt = 0;

    for (int t = 0; t < T; t++) {
        {   // gen0: z = h0 @ g0Whh^T
            GOp o0 = { g_h0f, 0, g_g0Whhf, 128, 32 };
            GOp o1 = { nullptr, 0, nullptr, 0, 0 };
            mma_tile(o0, o1, g_z, 4 * HGEN, mt, nt, smb, cnt);
        }
        gbar();
        for (int idx = bid * NTHR + tid; idx < B_ * HGEN; idx += NB * NTHR) {
            int b = idx >> 9, j = idx & (HGEN - 1);
            const float* zr = g_z + (size_t)b * 4 * HGEN;
            const float* tr = g_tabg0 + (size_t)g_tok[b] * 4 * HGEN;
            float zi = zr[j] + tr[j];
            float zf = zr[HGEN + j] + tr[HGEN + j];
            float zg = zr[2 * HGEN + j] + tr[2 * HGEN + j];
            float zo = zr[3 * HGEN + j] + tr[3 * HGEN + j];
            float c = sigf(zf) * g_c0d[idx] + sigf(zi) * tanhf(zg);
            g_c0d[idx] = c;
            frag_store(g_h0f, b, j, sigf(zo) * tanhf(c));
        }
        gbar();
        {   // gen1: z = h0 @ g1Wih^T + h1 @ g1Whh^T
            GOp o0 = { g_h0f,  0, g_g1Wihf, 128, 32 };
            GOp o1 = { g_h1df, 0, g_g1Whhf, 128, 32 };
            mma_tile(o0, o1, g_z, 4 * HGEN, mt, nt, smb, cnt);
        }
        gbar();
        for (int r = 0; r < 8; r++) {
            int row = bid * 8 + r;
            const float* zr = g_z + (size_t)row * 4 * HGEN;
            for (int j = tid; j < HGEN; j += NTHR) {
                float zi = zr[j] + g1b[j];
                float zf = zr[HGEN + j] + g1b[HGEN + j];
                float zg = zr[2 * HGEN + j] + g1b[2 * HGEN + j];
                float zo = zr[3 * HGEN + j] + g1b[3 * HGEN + j];
                size_t ix = (size_t)row * HGEN + j;
                float c = sigf(zf) * g_c1d[ix] + sigf(zi) * tanhf(zg);
                g_c1d[ix] = c;
                float h = sigf(zo) * tanhf(c);
                frag_store(g_h1df, row, j, h);
                sH[r * HGEN + j] = h;
            }
        }
        __syncthreads();
        {
            int w = tid >> 5, lane = tid & 31;
            int row = bid * 8 + w;
            float a0 = 0.f, a1 = 0.f, a2 = 0.f, a3 = 0.f, a4 = 0.f;
            for (int k = lane; k < HGEN; k += 32) {
                float hv = sH[w * HGEN + k];
                a0 += hv * outW[0 * HGEN + k];
                a1 += hv * outW[1 * HGEN + k];
                a2 += hv * outW[2 * HGEN + k];
                a3 += hv * outW[3 * HGEN + k];
                a4 += hv * outW[4 * HGEN + k];
            }
            #pragma unroll
            for (int off = 16; off; off >>= 1) {
                a0 += __shfl_down_sync(0xffffffffu, a0, off);
                a1 += __shfl_down_sync(0xffffffffu, a1, off);
                a2 += __shfl_down_sync(0xffffffffu, a2, off);
                a3 += __shfl_down_sync(0xffffffffu, a3, off);
                a4 += __shfl_down_sync(0xffffffffu, a4, off);
            }
            if (lane == 0) {
                float L0 = a0 + outb[0], L1 = a1 + outb[1], L2 = a2 + outb[2],
                      L3 = a3 + outb[3], L4 = a4 + outb[4];
                float* op = out + ((size_t)row * T + t) * VOC;
                op[0] = L0; op[1] = L1; op[2] = L2; op[3] = L3; op[4] = L4;
                int bi = 0; float best = L0;
                if (L1 > best) { best = L1; bi = 1; }
                if (L2 > best) { best = L2; bi = 2; }
                if (L3 > best) { best = L3; bi = 3; }
                if (L4 > best) { best = L4; bi = 4; }
                g_tok[row] = bi;
            }
        }
        gbar();
    }
}

// ---------------- orchestration ----------------
extern "C" void kernel_launch(void* const* d_in, const int* in_sizes, int n_in,
                              void* d_out, int out_size) {
    int ei = (in_sizes[2] == 1) ? 3 : 2;
    const int*   leftC  = (const int*)d_in[0];
    const int*   rightC = (const int*)d_in[1];
    const float* emb    = (const float*)d_in[ei + 0];
    const float* c0Wih  = (const float*)d_in[ei + 1];
    const float* c0Whh  = (const float*)d_in[ei + 2];
    const float* c0b    = (const float*)d_in[ei + 3];
    const float* c1Wih  = (const float*)d_in[ei + 4];
    const float* c1Whh  = (const float*)d_in[ei + 5];
    const float* c1b    = (const float*)d_in[ei + 6];
    const float* g0Wih  = (const float*)d_in[ei + 7];
    const float* g0Whh  = (const float*)d_in[ei + 8];
    const float* g0b    = (const float*)d_in[ei + 9];
    const float* g1Wih  = (const float*)d_in[ei + 10];
    const float* g1Whh  = (const float*)d_in[ei + 11];
    const float* g1b    = (const float*)d_in[ei + 12];
    const float* outW   = (const float*)d_in[ei + 13];
    const float* outb   = (const float*)d_in[ei + 14];
    float* out = (float*)d_out;

    const int L = in_sizes[0] / B_;       // 100
    const int T = out_size / (B_ * VOC);  // 256

    cudaFuncSetAttribute(encoder_kernel, cudaFuncAttributeMaxDynamicSharedMemorySize, SMEM_ENC);
    cudaFuncSetAttribute(decoder_kernel, cudaFuncAttributeMaxDynamicSharedMemorySize, SMEM_DEC);

    setup_kernel<<<512, 256>>>(emb, c0Wih, c0Whh, c0b, c1Wih, c1Whh,
                               g0Wih, g0Whh, g0b, g1Wih, g1Whh);
    encoder_kernel<<<NB, NTHR, SMEM_ENC>>>(leftC, rightC, c1b, L);
    decoder_kernel<<<NB, NTHR, SMEM_DEC>>>(g1b, outW, outb, out, T);
}